// round 3
// baseline (speedup 1.0000x reference)
#include <cuda_runtime.h>
#include <mma.h>
#include <math.h>
#include <stdint.h>

using namespace nvcuda;

// Problem constants (fixed shapes)
#define NN 100000
#define EE 1000000
#define F_IN 64
#define EMB 32
#define HH 4
#define CC 32
#define HCC 128
#define NEG_SLOPE 0.2f

// ---------------- scratch (device globals; no allocation allowed) ----------
__device__ float g_h [(size_t)NN * HCC];
__device__ float g_xl[(size_t)NN * HCC];
__device__ float g_xr[(size_t)NN * HCC];
__device__ float g_sk[(size_t)NN * HCC];
__device__ int   g_deg[NN];
__device__ int   g_rowptr[NN + 1];
__device__ int   g_cursor[NN];
__device__ int   g_csr[EE];
// packed per-layer weights: [K, 384] = Wl | Wr | Ws, and biases [384]
__device__ float g_Wf [EMB * 384];
__device__ float g_bf [384];
__device__ float g_Wm [HCC * 384];
__device__ float g_bm [384];
__device__ float g_Wl2[HCC * 384];
__device__ float g_bl2[384];

// ---------------- small utility kernels -----------------------------------
__global__ void zero_int_kernel(int* p, int n) {
    int i = blockIdx.x * blockDim.x + threadIdx.x;
    if (i < n) p[i] = 0;
}

__global__ void hist_kernel(const int* __restrict__ dst, int* __restrict__ deg, int e) {
    int i = blockIdx.x * blockDim.x + threadIdx.x;
    if (i < e) atomicAdd(&deg[dst[i]], 1);
}

// single-block exclusive scan over deg -> rowptr (+cursor copy), rowptr[n]=total
__global__ void scan_kernel(const int* __restrict__ deg, int* __restrict__ rowptr,
                            int* __restrict__ cursor, int n) {
    __shared__ int sums[1024];
    int tid = threadIdx.x;
    int chunk = (n + 1023) / 1024;
    int start = tid * chunk;
    int end   = min(start + chunk, n);
    int s = 0;
    for (int i = start; i < end; ++i) s += deg[i];
    sums[tid] = s;
    __syncthreads();
    for (int off = 1; off < 1024; off <<= 1) {
        int v = 0;
        if (tid >= off) v = sums[tid - off];
        __syncthreads();
        if (tid >= off) sums[tid] += v;
        __syncthreads();
    }
    int prefix = (tid == 0) ? 0 : sums[tid - 1];
    for (int i = start; i < end; ++i) {
        rowptr[i] = prefix;
        cursor[i] = prefix;
        prefix += deg[i];
    }
    if (tid == 1023) rowptr[n] = sums[1023];
}

__global__ void scatter_kernel(const int* __restrict__ src, const int* __restrict__ dst,
                               int* __restrict__ cursor, int* __restrict__ csr, int e) {
    int i = blockIdx.x * blockDim.x + threadIdx.x;
    if (i < e) {
        int d = dst[i];
        int pos = atomicAdd(&cursor[d], 1);
        csr[pos] = src[i];
    }
}

// pack Wl|Wr|Ws (each [K,128] row-major) -> Wp [K,384]; biases -> bp[384]
__global__ void pack_kernel(const float* __restrict__ Wl, const float* __restrict__ Wr,
                            const float* __restrict__ Ws,
                            const float* __restrict__ bl, const float* __restrict__ br,
                            const float* __restrict__ bs,
                            float* __restrict__ Wp, float* __restrict__ bp, int K) {
    int i = blockIdx.x * blockDim.x + threadIdx.x;
    int total = K * 128;
    if (i < total) {
        int k = i / 128, c = i % 128;
        Wp[(size_t)k * 384 + c]       = Wl[i];
        Wp[(size_t)k * 384 + 128 + c] = Wr[i];
        Wp[(size_t)k * 384 + 256 + c] = Ws[i];
    }
    if (i < 128) {
        bp[i]       = bl[i];
        bp[128 + i] = br[i];
        bp[256 + i] = bs[i];
    }
}

// ---------------- plain SGEMM (used once for x @ W0, tiny) -----------------
#define BM 128
#define BN 128
#define BK 16
#define TM 8
#define TN 8

__global__ __launch_bounds__(256, 2)
void gemm_bias_kernel(const float* __restrict__ A, const float* __restrict__ W,
                      const float* __restrict__ bias, float* __restrict__ C,
                      int M, int K, int Nc, int doRelu) {
    __shared__ float As[BK][BM + 4];
    __shared__ float Bs[BK][BN];

    int bm = blockIdx.x * BM;
    int bn = blockIdx.y * BN;
    int tid = threadIdx.x;
    int tx = tid & 15;
    int ty = tid >> 4;

    float acc[TM][TN];
#pragma unroll
    for (int i = 0; i < TM; ++i)
#pragma unroll
        for (int j = 0; j < TN; ++j) acc[i][j] = 0.f;

    for (int k0 = 0; k0 < K; k0 += BK) {
#pragma unroll
        for (int i = tid; i < BM * BK; i += 256) {
            int r = i / BK, c = i % BK;
            int gm = bm + r;
            As[c][r] = (gm < M) ? A[(size_t)gm * K + (k0 + c)] : 0.f;
        }
#pragma unroll
        for (int i = tid; i < BK * BN; i += 256) {
            int r = i / BN, c = i % BN;
            int gn = bn + c;
            Bs[r][c] = (gn < Nc) ? W[(size_t)(k0 + r) * Nc + gn] : 0.f;
        }
        __syncthreads();

#pragma unroll
        for (int kk = 0; kk < BK; ++kk) {
            float a[TM], b[TN];
            const float4* av = reinterpret_cast<const float4*>(&As[kk][ty * TM]);
            const float4* bv = reinterpret_cast<const float4*>(&Bs[kk][tx * TN]);
            float4 a0 = av[0], a1 = av[1];
            float4 b0 = bv[0], b1 = bv[1];
            a[0]=a0.x; a[1]=a0.y; a[2]=a0.z; a[3]=a0.w;
            a[4]=a1.x; a[5]=a1.y; a[6]=a1.z; a[7]=a1.w;
            b[0]=b0.x; b[1]=b0.y; b[2]=b0.z; b[3]=b0.w;
            b[4]=b1.x; b[5]=b1.y; b[6]=b1.z; b[7]=b1.w;
#pragma unroll
            for (int i = 0; i < TM; ++i)
#pragma unroll
                for (int j = 0; j < TN; ++j) acc[i][j] += a[i] * b[j];
        }
        __syncthreads();
    }

#pragma unroll
    for (int i = 0; i < TM; ++i) {
        int gm = bm + ty * TM + i;
        if (gm >= M) continue;
#pragma unroll
        for (int j = 0; j < TN; ++j) {
            int gn = bn + tx * TN + j;
            if (gn >= Nc) continue;
            float v = acc[i][j] + (bias ? bias[gn] : 0.f);
            if (doRelu) v = fmaxf(v, 0.f);
            C[(size_t)gm * Nc + gn] = v;
        }
    }
}

// ---------------- fused tf32 tensor-core GEMM ------------------------------
// C[M, 384] = A[M, K] @ Wp[K, 384] + bp; column blocks 0/1->xl, 2/3->xr, 4/5->sk
#define GM 128
#define GN 64
#define GK 16
#define A_LD (GK + 8)
#define B_LD (GN + 8)
#define S_LD 20

__global__ __launch_bounds__(256, 2)
void gemm_tf32_fused(const float* __restrict__ A, const float* __restrict__ Wp,
                     const float* __restrict__ bp,
                     float* __restrict__ xl, float* __restrict__ xr,
                     float* __restrict__ sk, int M, int K) {
    __shared__ float As[GM][A_LD];
    __shared__ float Bs[GK][B_LD];
    __shared__ float stage[8][16][S_LD];

    int bm = blockIdx.x * GM;
    int bn = blockIdx.y * GN;   // global col offset in [0, 384)
    int tid = threadIdx.x;
    int warp = tid >> 5;
    int lane = tid & 31;
    int wm = warp >> 1;   // 0..3  (row tile of 32)
    int wn = warp & 1;    // 0..1  (col tile of 32)

    wmma::fragment<wmma::accumulator, 16, 16, 8, float> fc[2][2];
#pragma unroll
    for (int i = 0; i < 2; ++i)
#pragma unroll
        for (int j = 0; j < 2; ++j) wmma::fill_fragment(fc[i][j], 0.f);

    for (int k0 = 0; k0 < K; k0 += GK) {
        // A tile: 128 x 16  (256 threads x 8 elems)
        {
            int r = tid >> 1, c0 = (tid & 1) * 8;
            int gm = bm + r;
            const float* ap = A + (size_t)gm * K + k0 + c0;
#pragma unroll
            for (int u = 0; u < 8; ++u)
                As[r][c0 + u] = (gm < M) ? wmma::__float_to_tf32(ap[u]) : 0.f;
        }
        // B tile: 16 x 64  (256 threads x 4 elems)
        {
            int r = tid >> 4, c0 = (tid & 15) * 4;
            const float* wp = Wp + (size_t)(k0 + r) * 384 + bn + c0;
#pragma unroll
            for (int u = 0; u < 4; ++u)
                Bs[r][c0 + u] = wmma::__float_to_tf32(wp[u]);
        }
        __syncthreads();

#pragma unroll
        for (int kk = 0; kk < GK; kk += 8) {
            wmma::fragment<wmma::matrix_a, 16, 16, 8, wmma::precision::tf32, wmma::row_major> fa0, fa1;
            wmma::fragment<wmma::matrix_b, 16, 16, 8, wmma::precision::tf32, wmma::row_major> fb0, fb1;
            wmma::load_matrix_sync(fa0, &As[wm * 32][kk], A_LD);
            wmma::load_matrix_sync(fa1, &As[wm * 32 + 16][kk], A_LD);
            wmma::load_matrix_sync(fb0, &Bs[kk][wn * 32], B_LD);
            wmma::load_matrix_sync(fb1, &Bs[kk][wn * 32 + 16], B_LD);
            wmma::mma_sync(fc[0][0], fa0, fb0, fc[0][0]);
            wmma::mma_sync(fc[0][1], fa0, fb1, fc[0][1]);
            wmma::mma_sync(fc[1][0], fa1, fb0, fc[1][0]);
            wmma::mma_sync(fc[1][1], fa1, fb1, fc[1][1]);
        }
        __syncthreads();
    }

    // epilogue: stage per-warp 16x16 tiles through smem, add bias, route output
#pragma unroll
    for (int i = 0; i < 2; ++i) {
#pragma unroll
        for (int j = 0; j < 2; ++j) {
            wmma::store_matrix_sync(&stage[warp][0][0], fc[i][j], S_LD, wmma::mem_row_major);
            __syncwarp();
            int r0 = bm + wm * 32 + i * 16;
            int c0 = bn + wn * 32 + j * 16;
#pragma unroll
            for (int t = lane; t < 256; t += 32) {
                int lr = t >> 4, lc = t & 15;
                int gm = r0 + lr;
                int gc = c0 + lc;      // 0..383
                if (gm < M) {
                    float v = stage[warp][lr][lc] + bp[gc];
                    int sel = gc >> 7;         // 0,1,2
                    int cc = gc & 127;
                    float* outp = (sel == 0) ? xl : ((sel == 1) ? xr : sk);
                    outp[(size_t)gm * HCC + cc] = v;
                }
            }
            __syncwarp();
        }
    }
}

// ---------------- GAT edge kernel: one warp per dst node, online softmax ---
__global__ __launch_bounds__(256)
void gat_edge_kernel(const int* __restrict__ rowptr, const int* __restrict__ csr,
                     const float* __restrict__ xl, const float* __restrict__ xr,
                     const float* __restrict__ skip,
                     const float* __restrict__ att, const float* __restrict__ cb,
                     float* __restrict__ out, int n, int doRelu, int doNorm) {
    int warp_id = (blockIdx.x * blockDim.x + threadIdx.x) >> 5;
    if (warp_id >= n) return;
    int lane = threadIdx.x & 31;
    int node = warp_id;

    float xrv[HH], attv[HH];
#pragma unroll
    for (int h = 0; h < HH; ++h) {
        xrv[h]  = __ldg(&xr[(size_t)node * HCC + h * CC + lane]);
        attv[h] = __ldg(&att[h * CC + lane]);
    }

    float m[HH], den[HH], acc[HH];
#pragma unroll
    for (int h = 0; h < HH; ++h) { m[h] = -INFINITY; den[h] = 0.f; acc[h] = 0.f; }

    int e0 = rowptr[node];
    int e1 = rowptr[node + 1];
    for (int e = e0; e < e1; ++e) {
        int src = csr[e];
        float xlv[HH], s[HH];
#pragma unroll
        for (int h = 0; h < HH; ++h)
            xlv[h] = __ldg(&xl[(size_t)src * HCC + h * CC + lane]);
#pragma unroll
        for (int h = 0; h < HH; ++h) {
            float t = xlv[h] + xrv[h];
            t = (t > 0.f) ? t : NEG_SLOPE * t;
            s[h] = t * attv[h];
        }
#pragma unroll
        for (int off = 16; off > 0; off >>= 1) {
#pragma unroll
            for (int h = 0; h < HH; ++h)
                s[h] += __shfl_xor_sync(0xffffffffu, s[h], off);
        }
#pragma unroll
        for (int h = 0; h < HH; ++h) {
            float nm = fmaxf(m[h], s[h]);
            float scale = __expf(m[h] - nm);
            float p = __expf(s[h] - nm);
            den[h] = den[h] * scale + p;
            acc[h] = acc[h] * scale + p * xlv[h];
            m[h] = nm;
        }
    }

    float o[HH];
#pragma unroll
    for (int h = 0; h < HH; ++h) {
        float g = (den[h] > 0.f) ? (acc[h] / den[h]) : 0.f;
        o[h] = g + __ldg(&cb[h * CC + lane]) + skip[(size_t)node * HCC + h * CC + lane];
        if (doRelu) o[h] = fmaxf(o[h], 0.f);
    }
    if (doNorm) {
        float sq = 0.f;
#pragma unroll
        for (int h = 0; h < HH; ++h) sq += o[h] * o[h];
#pragma unroll
        for (int off = 16; off > 0; off >>= 1)
            sq += __shfl_xor_sync(0xffffffffu, sq, off);
        float inv = rsqrtf(sq);
#pragma unroll
        for (int h = 0; h < HH; ++h) o[h] *= inv;
    }
#pragma unroll
    for (int h = 0; h < HH; ++h)
        out[(size_t)node * HCC + h * CC + lane] = o[h];
}

// ---------------- host ------------------------------------------------------
extern "C" void kernel_launch(void* const* d_in, const int* in_sizes, int n_in,
                              void* d_out, int out_size) {
    const float* x  = (const float*)d_in[0];
    const int*   ei = (const int*)d_in[1];
    const float* W0 = (const float*)d_in[2];

    // f: 3..10, m: 11..18, l: 19..26 (order: Wl, bl, Wr, br, att, cb, Ws, bs)
    const float* P[27];
    for (int i = 3; i < 27; ++i) P[i] = (const float*)d_in[i];

    float *h, *xl, *xr, *sk;
    float *Wf, *bf, *Wm, *bm_, *Wl2, *bl2;
    int *deg, *rowptr, *cursor, *csr;
    cudaGetSymbolAddress((void**)&h,      g_h);
    cudaGetSymbolAddress((void**)&xl,     g_xl);
    cudaGetSymbolAddress((void**)&xr,     g_xr);
    cudaGetSymbolAddress((void**)&sk,     g_sk);
    cudaGetSymbolAddress((void**)&deg,    g_deg);
    cudaGetSymbolAddress((void**)&rowptr, g_rowptr);
    cudaGetSymbolAddress((void**)&cursor, g_cursor);
    cudaGetSymbolAddress((void**)&csr,    g_csr);
    cudaGetSymbolAddress((void**)&Wf,     g_Wf);
    cudaGetSymbolAddress((void**)&bf,     g_bf);
    cudaGetSymbolAddress((void**)&Wm,     g_Wm);
    cudaGetSymbolAddress((void**)&bm_,    g_bm);
    cudaGetSymbolAddress((void**)&Wl2,    g_Wl2);
    cudaGetSymbolAddress((void**)&bl2,    g_bl2);

    const int* src = ei;
    const int* dst = ei + EE;

    // ---- CSR build (by dst) ----
    zero_int_kernel<<<(NN + 255) / 256, 256>>>(deg, NN);
    hist_kernel<<<(EE + 255) / 256, 256>>>(dst, deg, EE);
    scan_kernel<<<1, 1024>>>(deg, rowptr, cursor, NN);
    scatter_kernel<<<(EE + 255) / 256, 256>>>(src, dst, cursor, csr, EE);

    // ---- pack per-layer weights ----
    pack_kernel<<<(EMB * 128 + 255) / 256, 256>>>(P[3], P[5], P[9], P[4], P[6], P[10], Wf, bf, EMB);
    pack_kernel<<<(HCC * 128 + 255) / 256, 256>>>(P[11], P[13], P[17], P[12], P[14], P[18], Wm, bm_, HCC);
    pack_kernel<<<(HCC * 128 + 255) / 256, 256>>>(P[19], P[21], P[25], P[20], P[22], P[26], Wl2, bl2, HCC);

    // h0 = relu(x @ W0)  [N, 32]
    dim3 g0((NN + BM - 1) / BM, 1);
    gemm_bias_kernel<<<g0, 256>>>(x, W0, nullptr, h, NN, F_IN, EMB, 1);

    dim3 fused_grid((NN + GM - 1) / GM, 384 / GN);
    int edge_blocks = (NN * 32 + 255) / 256;

    auto run_layer = [&](const float* Wp, const float* bp, int K,
                         const float* att, const float* cb,
                         int doRelu, int doNorm, float* outp) {
        gemm_tf32_fused<<<fused_grid, 256>>>(h, Wp, bp, xl, xr, sk, NN, K);
        gat_edge_kernel<<<edge_blocks, 256>>>(rowptr, csr, xl, xr, sk, att, cb,
                                              outp, NN, doRelu, doNorm);
    };

    run_layer(Wf,  bf,  EMB, P[7],  P[8],  1, 0, h);    // first GAT layer (K=32)
    run_layer(Wm,  bm_, HCC, P[15], P[16], 1, 0, h);    // mid x3 (shared weights)
    run_layer(Wm,  bm_, HCC, P[15], P[16], 1, 0, h);
    run_layer(Wm,  bm_, HCC, P[15], P[16], 1, 0, h);
    run_layer(Wl2, bl2, HCC, P[23], P[24], 0, 1, (float*)d_out);  // last + L2 norm
}

// round 7
// speedup vs baseline: 1.9041x; 1.9041x over previous
#include <cuda_runtime.h>
#include <cuda_fp16.h>
#include <mma.h>
#include <math.h>
#include <stdint.h>

using namespace nvcuda;

// Problem constants (fixed shapes)
#define NN 100000
#define EE 1000000
#define F_IN 64
#define EMB 32
#define HH 4
#define CC 32
#define HCC 128
#define NEG_SLOPE 0.2f

// ---------------- scratch (device globals; no allocation allowed) ----------
__device__ __align__(16) __half g_hh[(size_t)NN * HCC];   // fp16 activations
__device__ float g_xl[(size_t)NN * HCC];
__device__ float g_xr[(size_t)NN * HCC];
__device__ float g_sk[(size_t)NN * HCC];
__device__ int   g_deg[NN];
__device__ int   g_rowptr[NN + 1];
__device__ int   g_cursor[NN];
__device__ int   g_csr[EE];
// packed per-layer weights fp16: Wp[K, 384] = Wl | Wr | Ws ; biases fp32 [384]
__device__ __align__(16) __half g_Wf [EMB * 384];
__device__ float g_bf [384];
__device__ __align__(16) __half g_Wm [HCC * 384];
__device__ float g_bm [384];
__device__ __align__(16) __half g_Wl2[HCC * 384];
__device__ float g_bl2[384];

// ---------------- small utility kernels -----------------------------------
__global__ void zero_int_kernel(int* p, int n) {
    int i = blockIdx.x * blockDim.x + threadIdx.x;
    if (i < n) p[i] = 0;
}

__global__ void hist_kernel(const int* __restrict__ dst, int* __restrict__ deg, int e) {
    int i = blockIdx.x * blockDim.x + threadIdx.x;
    if (i < e) atomicAdd(&deg[dst[i]], 1);
}

__global__ void scan_kernel(const int* __restrict__ deg, int* __restrict__ rowptr,
                            int* __restrict__ cursor, int n) {
    __shared__ int sums[1024];
    int tid = threadIdx.x;
    int chunk = (n + 1023) / 1024;
    int start = tid * chunk;
    int end   = min(start + chunk, n);
    int s = 0;
    for (int i = start; i < end; ++i) s += deg[i];
    sums[tid] = s;
    __syncthreads();
    for (int off = 1; off < 1024; off <<= 1) {
        int v = 0;
        if (tid >= off) v = sums[tid - off];
        __syncthreads();
        if (tid >= off) sums[tid] += v;
        __syncthreads();
    }
    int prefix = (tid == 0) ? 0 : sums[tid - 1];
    for (int i = start; i < end; ++i) {
        rowptr[i] = prefix;
        cursor[i] = prefix;
        prefix += deg[i];
    }
    if (tid == 1023) rowptr[n] = sums[1023];
}

__global__ void scatter_kernel(const int* __restrict__ src, const int* __restrict__ dst,
                               int* __restrict__ cursor, int* __restrict__ csr, int e) {
    int i = blockIdx.x * blockDim.x + threadIdx.x;
    if (i < e) {
        int d = dst[i];
        int pos = atomicAdd(&cursor[d], 1);
        csr[pos] = src[i];
    }
}

// pack Wl|Wr|Ws (each [K,128] row-major fp32) -> fp16 Wp [K,384]; biases fp32
__global__ void pack_h_kernel(const float* __restrict__ Wl, const float* __restrict__ Wr,
                              const float* __restrict__ Ws,
                              const float* __restrict__ bl, const float* __restrict__ br,
                              const float* __restrict__ bs,
                              __half* __restrict__ Wp, float* __restrict__ bp, int K) {
    int i = blockIdx.x * blockDim.x + threadIdx.x;
    int total = K * 128;
    if (i < total) {
        int k = i / 128, c = i % 128;
        Wp[(size_t)k * 384 + c]       = __float2half(Wl[i]);
        Wp[(size_t)k * 384 + 128 + c] = __float2half(Wr[i]);
        Wp[(size_t)k * 384 + 256 + c] = __float2half(Ws[i]);
    }
    if (i < 128) {
        bp[i]       = bl[i];
        bp[128 + i] = br[i];
        bp[256 + i] = bs[i];
    }
}

// ---------------- plain SGEMM for x @ W0 -> relu -> fp16 h0 ----------------
#define BM 128
#define BN 32
#define BK 16

__global__ __launch_bounds__(256, 2)
void gemm0_kernel(const float* __restrict__ A, const float* __restrict__ W,
                  __half* __restrict__ C, int M, int K, int Nc) {
    __shared__ float As[BK][BM + 4];
    __shared__ float Bs[BK][BN];

    int bm = blockIdx.x * BM;
    int tid = threadIdx.x;
    int tx = tid & 7;          // 0..7   -> n (4 cols each)
    int ty = tid >> 3;         // 0..31  -> m (4 rows each)

    float acc[4][4];
#pragma unroll
    for (int i = 0; i < 4; ++i)
#pragma unroll
        for (int j = 0; j < 4; ++j) acc[i][j] = 0.f;

    for (int k0 = 0; k0 < K; k0 += BK) {
#pragma unroll
        for (int i = tid; i < BM * BK; i += 256) {
            int r = i / BK, c = i % BK;
            int gm = bm + r;
            As[c][r] = (gm < M) ? A[(size_t)gm * K + (k0 + c)] : 0.f;
        }
#pragma unroll
        for (int i = tid; i < BK * BN; i += 256) {
            int r = i / BN, c = i % BN;
            Bs[r][c] = W[(size_t)(k0 + r) * Nc + c];
        }
        __syncthreads();

#pragma unroll
        for (int kk = 0; kk < BK; ++kk) {
            float a[4], b[4];
#pragma unroll
            for (int i = 0; i < 4; ++i) a[i] = As[kk][ty * 4 + i];
#pragma unroll
            for (int j = 0; j < 4; ++j) b[j] = Bs[kk][tx * 4 + j];
#pragma unroll
            for (int i = 0; i < 4; ++i)
#pragma unroll
                for (int j = 0; j < 4; ++j) acc[i][j] += a[i] * b[j];
        }
        __syncthreads();
    }

#pragma unroll
    for (int i = 0; i < 4; ++i) {
        int gm = bm + ty * 4 + i;
        if (gm >= M) continue;
#pragma unroll
        for (int j = 0; j < 4; ++j) {
            int gn = tx * 4 + j;
            float v = fmaxf(acc[i][j], 0.f);
            C[(size_t)gm * Nc + gn] = __float2half(v);
        }
    }
}

// ---------------- fp16 wmma GEMM ------------------------------------------
// out[M, 128-block sel] = A[M,K](fp16) @ Wp[K,384](fp16) + bias
// CTA tile 128x128; blockIdx.y = sel (0:xl, 1:xr, 2:sk). K in {32, 128}.
#define A_LDH 40
#define B_LDH 136

__global__ __launch_bounds__(256, 2)
void gemm_h16_kernel(const __half* __restrict__ A, const __half* __restrict__ B,
                     const float* __restrict__ bias,
                     float* __restrict__ xl, float* __restrict__ xr,
                     float* __restrict__ sk, int M, int K) {
    __shared__ __align__(16) __half As[128 * A_LDH];
    __shared__ __align__(16) __half Bs[32 * B_LDH];
    __shared__ float stage[8][16 * 20];

    const int tid = threadIdx.x;
    const int warp = tid >> 5;
    const int lane = tid & 31;
    const int wm = warp >> 1;     // 0..3: rows wm*32
    const int wn = warp & 1;      // 0..1: cols wn*64
    const int bm = blockIdx.x * 128;
    const int sel = blockIdx.y;   // 0,1,2
    const int bn = sel * 128;

    // per-thread staging coordinates
    const int ar = tid >> 2, ac = (tid & 3) * 8;          // A: 128 rows x 32 cols
    const int br_ = tid >> 4, bc = (tid & 15) * 8;        // B: 32 rows x 128 cols (wait: 16*8=128) 

    wmma::fragment<wmma::accumulator, 16, 16, 16, float> fc[2][4];
#pragma unroll
    for (int i = 0; i < 2; ++i)
#pragma unroll
        for (int j = 0; j < 4; ++j) wmma::fill_fragment(fc[i][j], 0.f);

    const int nch = K >> 5;

    for (int ch = 0; ch < nch; ++ch) {
        const int k0 = ch << 5;
        // A tile: each thread 2 rows (ar, ar+64), 8 halves each
        {
            int gm0 = bm + ar;
            int gm1 = bm + ar + 64;
            uint4 v0 = make_uint4(0, 0, 0, 0), v1 = make_uint4(0, 0, 0, 0);
            if (gm0 < M) v0 = *reinterpret_cast<const uint4*>(A + (size_t)gm0 * K + k0 + ac);
            if (gm1 < M) v1 = *reinterpret_cast<const uint4*>(A + (size_t)gm1 * K + k0 + ac);
            *reinterpret_cast<uint4*>(&As[ar * A_LDH + ac]) = v0;
            *reinterpret_cast<uint4*>(&As[(ar + 64) * A_LDH + ac]) = v1;
        }
        // B tile: each thread 2 rows (br_, br_+16), 8 halves each
        {
            uint4 v0 = *reinterpret_cast<const uint4*>(B + (size_t)(k0 + br_) * 384 + bn + bc);
            uint4 v1 = *reinterpret_cast<const uint4*>(B + (size_t)(k0 + br_ + 16) * 384 + bn + bc);
            *reinterpret_cast<uint4*>(&Bs[br_ * B_LDH + bc]) = v0;
            *reinterpret_cast<uint4*>(&Bs[(br_ + 16) * B_LDH + bc]) = v1;
        }
        __syncthreads();

#pragma unroll
        for (int kk = 0; kk < 32; kk += 16) {
            wmma::fragment<wmma::matrix_a, 16, 16, 16, __half, wmma::row_major> fa[2];
            wmma::fragment<wmma::matrix_b, 16, 16, 16, __half, wmma::row_major> fb[4];
#pragma unroll
            for (int i = 0; i < 2; ++i)
                wmma::load_matrix_sync(fa[i], &As[(wm * 32 + i * 16) * A_LDH + kk], A_LDH);
#pragma unroll
            for (int j = 0; j < 4; ++j)
                wmma::load_matrix_sync(fb[j], &Bs[kk * B_LDH + wn * 64 + j * 16], B_LDH);
#pragma unroll
            for (int i = 0; i < 2; ++i)
#pragma unroll
                for (int j = 0; j < 4; ++j)
                    wmma::mma_sync(fc[i][j], fa[i], fb[j], fc[i][j]);
        }
        __syncthreads();
    }

    float* outp = (sel == 0) ? xl : ((sel == 1) ? xr : sk);

#pragma unroll
    for (int i = 0; i < 2; ++i) {
#pragma unroll
        for (int j = 0; j < 4; ++j) {
            wmma::store_matrix_sync(&stage[warp][0], fc[i][j], 20, wmma::mem_row_major);
            __syncwarp();
            int r0 = bm + wm * 32 + i * 16;
            int c0 = wn * 64 + j * 16;        // local col in [0,128)
#pragma unroll
            for (int t = lane; t < 256; t += 32) {
                int lr = t >> 4, lc = t & 15;
                int gm = r0 + lr;
                if (gm < M)
                    outp[(size_t)gm * HCC + c0 + lc] =
                        stage[warp][lr * 20 + lc] + __ldg(&bias[bn + c0 + lc]);
            }
            __syncwarp();
        }
    }
}

// ---------------- GAT edge kernel: one warp per dst node, online softmax ---
// writes fp16 h (mid layers) or fp32 normalized output (final layer)
__global__ __launch_bounds__(256)
void gat_edge_kernel(const int* __restrict__ rowptr, const int* __restrict__ csr,
                     const float* __restrict__ xl, const float* __restrict__ xr,
                     const float* __restrict__ skip,
                     const float* __restrict__ att, const float* __restrict__ cb,
                     __half* __restrict__ outh, float* __restrict__ outf, int n) {
    int warp_id = (blockIdx.x * blockDim.x + threadIdx.x) >> 5;
    if (warp_id >= n) return;
    int lane = threadIdx.x & 31;
    int node = warp_id;

    float xrv[HH], attv[HH];
#pragma unroll
    for (int h = 0; h < HH; ++h) {
        xrv[h]  = __ldg(&xr[(size_t)node * HCC + h * CC + lane]);
        attv[h] = __ldg(&att[h * CC + lane]);
    }

    float m[HH], den[HH], acc[HH];
#pragma unroll
    for (int h = 0; h < HH; ++h) { m[h] = -INFINITY; den[h] = 0.f; acc[h] = 0.f; }

    int e0 = rowptr[node];
    int e1 = rowptr[node + 1];
    for (int e = e0; e < e1; ++e) {
        int src = csr[e];
        float xlv[HH], s[HH];
#pragma unroll
        for (int h = 0; h < HH; ++h)
            xlv[h] = __ldg(&xl[(size_t)src * HCC + h * CC + lane]);
#pragma unroll
        for (int h = 0; h < HH; ++h) {
            float t = xlv[h] + xrv[h];
            t = (t > 0.f) ? t : NEG_SLOPE * t;
            s[h] = t * attv[h];
        }
#pragma unroll
        for (int off = 16; off > 0; off >>= 1) {
#pragma unroll
            for (int h = 0; h < HH; ++h)
                s[h] += __shfl_xor_sync(0xffffffffu, s[h], off);
        }
#pragma unroll
        for (int h = 0; h < HH; ++h) {
            float nm = fmaxf(m[h], s[h]);
            float scale = __expf(m[h] - nm);
            float p = __expf(s[h] - nm);
            den[h] = den[h] * scale + p;
            acc[h] = acc[h] * scale + p * xlv[h];
            m[h] = nm;
        }
    }

    float o[HH];
#pragma unroll
    for (int h = 0; h < HH; ++h) {
        float g = (den[h] > 0.f) ? (acc[h] / den[h]) : 0.f;
        o[h] = g + __ldg(&cb[h * CC + lane]) + skip[(size_t)node * HCC + h * CC + lane];
    }
    if (outh) {
        // mid layer: relu, write fp16
#pragma unroll
        for (int h = 0; h < HH; ++h)
            outh[(size_t)node * HCC + h * CC + lane] = __float2half(fmaxf(o[h], 0.f));
    } else {
        // final layer: L2 normalize, write fp32
        float sq = 0.f;
#pragma unroll
        for (int h = 0; h < HH; ++h) sq += o[h] * o[h];
#pragma unroll
        for (int off = 16; off > 0; off >>= 1)
            sq += __shfl_xor_sync(0xffffffffu, sq, off);
        float inv = rsqrtf(sq);
#pragma unroll
        for (int h = 0; h < HH; ++h)
            outf[(size_t)node * HCC + h * CC + lane] = o[h] * inv;
    }
}

// ---------------- host ------------------------------------------------------
extern "C" void kernel_launch(void* const* d_in, const int* in_sizes, int n_in,
                              void* d_out, int out_size) {
    const float* x  = (const float*)d_in[0];
    const int*   ei = (const int*)d_in[1];
    const float* W0 = (const float*)d_in[2];

    // f: 3..10, m: 11..18, l: 19..26 (order: Wl, bl, Wr, br, att, cb, Ws, bs)
    const float* P[27];
    for (int i = 3; i < 27; ++i) P[i] = (const float*)d_in[i];

    __half *hh, *Wf, *Wm, *Wl2;
    float *xl, *xr, *sk, *bf, *bm_, *bl2;
    int *deg, *rowptr, *cursor, *csr;
    cudaGetSymbolAddress((void**)&hh,     g_hh);
    cudaGetSymbolAddress((void**)&xl,     g_xl);
    cudaGetSymbolAddress((void**)&xr,     g_xr);
    cudaGetSymbolAddress((void**)&sk,     g_sk);
    cudaGetSymbolAddress((void**)&deg,    g_deg);
    cudaGetSymbolAddress((void**)&rowptr, g_rowptr);
    cudaGetSymbolAddress((void**)&cursor, g_cursor);
    cudaGetSymbolAddress((void**)&csr,    g_csr);
    cudaGetSymbolAddress((void**)&Wf,     g_Wf);
    cudaGetSymbolAddress((void**)&bf,     g_bf);
    cudaGetSymbolAddress((void**)&Wm,     g_Wm);
    cudaGetSymbolAddress((void**)&bm_,    g_bm);
    cudaGetSymbolAddress((void**)&Wl2,    g_Wl2);
    cudaGetSymbolAddress((void**)&bl2,    g_bl2);

    const int* src = ei;
    const int* dst = ei + EE;

    // ---- CSR build (by dst) ----
    zero_int_kernel<<<(NN + 255) / 256, 256>>>(deg, NN);
    hist_kernel<<<(EE + 255) / 256, 256>>>(dst, deg, EE);
    scan_kernel<<<1, 1024>>>(deg, rowptr, cursor, NN);
    scatter_kernel<<<(EE + 255) / 256, 256>>>(src, dst, cursor, csr, EE);

    // ---- pack per-layer weights to fp16 ----
    pack_h_kernel<<<(EMB * 128 + 255) / 256, 256>>>(P[3], P[5], P[9], P[4], P[6], P[10], Wf, bf, EMB);
    pack_h_kernel<<<(HCC * 128 + 255) / 256, 256>>>(P[11], P[13], P[17], P[12], P[14], P[18], Wm, bm_, HCC);
    pack_h_kernel<<<(HCC * 128 + 255) / 256, 256>>>(P[19], P[21], P[25], P[20], P[22], P[26], Wl2, bl2, HCC);

    // h0 = relu(x @ W0)  [N, 32] fp16
    gemm0_kernel<<<(NN + BM - 1) / BM, 256>>>(x, W0, hh, NN, F_IN, EMB);

    dim3 wgrid((NN + 127) / 128, 3);
    int edge_blocks = (NN * 32 + 255) / 256;

    auto run_layer = [&](const __half* Wp, const float* bp, int K,
                         const float* att, const float* cb,
                         __half* outh, float* outf) {
        gemm_h16_kernel<<<wgrid, 256>>>(hh, Wp, bp, xl, xr, sk, NN, K);
        gat_edge_kernel<<<edge_blocks, 256>>>(rowptr, csr, xl, xr, sk, att, cb,
                                              outh, outf, NN);
    };

    run_layer(Wf,  bf,  EMB, P[7],  P[8],  hh, nullptr);   // first GAT layer (K=32)
    run_layer(Wm,  bm_, HCC, P[15], P[16], hh, nullptr);   // mid x3 (shared weights)
    run_layer(Wm,  bm_, HCC, P[15], P[16], hh, nullptr);
    run_layer(Wm,  bm_, HCC, P[15], P[16], hh, nullptr);
    run_layer(Wl2, bl2, HCC, P[23], P[24], nullptr, (float*)d_out);  // last + L2 norm
}

// round 9
// speedup vs baseline: 2.9804x; 1.5653x over previous
#include <cuda_runtime.h>
#include <cuda_fp16.h>
#include <mma.h>
#include <math.h>
#include <stdint.h>

using namespace nvcuda;

// Problem constants (fixed shapes)
#define NN 100000
#define EE 1000000
#define F_IN 64
#define EMB 32
#define HH 4
#define CC 32
#define HCC 128
#define NEG_SLOPE 0.2f

// ---------------- scratch (device globals; no allocation allowed) ----------
__device__ __align__(16) __half g_hh[(size_t)NN * HCC];   // fp16 activations
__device__ __align__(16) __half g_xl[(size_t)NN * HCC];
__device__ __align__(16) __half g_xr[(size_t)NN * HCC];
__device__ __align__(16) __half g_sk[(size_t)NN * HCC];
__device__ int   g_deg[NN];
__device__ int   g_rowptr[NN + 1];
__device__ int   g_cursor[NN];
__device__ int   g_csr[EE];
// packed per-layer weights fp16: Wp[K, 384] = Wl | Wr | Ws ; biases fp32 [384]
__device__ __align__(16) __half g_Wf [EMB * 384];
__device__ float g_bf [384];
__device__ __align__(16) __half g_Wm [HCC * 384];
__device__ float g_bm [384];
__device__ __align__(16) __half g_Wl2[HCC * 384];
__device__ float g_bl2[384];

// ---------------- small utility kernels -----------------------------------
__global__ void zero_int_kernel(int* p, int n) {
    int i = blockIdx.x * blockDim.x + threadIdx.x;
    if (i < n) p[i] = 0;
}

__global__ void hist_kernel(const int* __restrict__ dst, int* __restrict__ deg, int e) {
    int i = blockIdx.x * blockDim.x + threadIdx.x;
    if (i < e) atomicAdd(&deg[dst[i]], 1);
}

__global__ void scan_kernel(const int* __restrict__ deg, int* __restrict__ rowptr,
                            int* __restrict__ cursor, int n) {
    __shared__ int sums[1024];
    int tid = threadIdx.x;
    int chunk = (n + 1023) / 1024;
    int start = tid * chunk;
    int end   = min(start + chunk, n);
    int s = 0;
    for (int i = start; i < end; ++i) s += deg[i];
    sums[tid] = s;
    __syncthreads();
    for (int off = 1; off < 1024; off <<= 1) {
        int v = 0;
        if (tid >= off) v = sums[tid - off];
        __syncthreads();
        if (tid >= off) sums[tid] += v;
        __syncthreads();
    }
    int prefix = (tid == 0) ? 0 : sums[tid - 1];
    for (int i = start; i < end; ++i) {
        rowptr[i] = prefix;
        cursor[i] = prefix;
        prefix += deg[i];
    }
    if (tid == 1023) rowptr[n] = sums[1023];
}

__global__ void scatter_kernel(const int* __restrict__ src, const int* __restrict__ dst,
                               int* __restrict__ cursor, int* __restrict__ csr, int e) {
    int i = blockIdx.x * blockDim.x + threadIdx.x;
    if (i < e) {
        int d = dst[i];
        int pos = atomicAdd(&cursor[d], 1);
        csr[pos] = src[i];
    }
}

// pack Wl|Wr|Ws (each [K,128] row-major fp32) -> fp16 Wp [K,384]; biases fp32
__global__ void pack_h_kernel(const float* __restrict__ Wl, const float* __restrict__ Wr,
                              const float* __restrict__ Ws,
                              const float* __restrict__ bl, const float* __restrict__ br,
                              const float* __restrict__ bs,
                              __half* __restrict__ Wp, float* __restrict__ bp, int K) {
    int i = blockIdx.x * blockDim.x + threadIdx.x;
    int total = K * 128;
    if (i < total) {
        int k = i / 128, c = i % 128;
        Wp[(size_t)k * 384 + c]       = __float2half(Wl[i]);
        Wp[(size_t)k * 384 + 128 + c] = __float2half(Wr[i]);
        Wp[(size_t)k * 384 + 256 + c] = __float2half(Ws[i]);
    }
    if (i < 128) {
        bp[i]       = bl[i];
        bp[128 + i] = br[i];
        bp[256 + i] = bs[i];
    }
}

// ---------------- plain SGEMM for x @ W0 -> relu -> fp16 h0 ----------------
#define BM 128
#define BN 32
#define BK 16

__global__ __launch_bounds__(256, 2)
void gemm0_kernel(const float* __restrict__ A, const float* __restrict__ W,
                  __half* __restrict__ C, int M, int K, int Nc) {
    __shared__ float As[BK][BM + 4];
    __shared__ float Bs[BK][BN];

    int bm = blockIdx.x * BM;
    int tid = threadIdx.x;
    int tx = tid & 7;
    int ty = tid >> 3;

    float acc[4][4];
#pragma unroll
    for (int i = 0; i < 4; ++i)
#pragma unroll
        for (int j = 0; j < 4; ++j) acc[i][j] = 0.f;

    for (int k0 = 0; k0 < K; k0 += BK) {
#pragma unroll
        for (int i = tid; i < BM * BK; i += 256) {
            int r = i / BK, c = i % BK;
            int gm = bm + r;
            As[c][r] = (gm < M) ? A[(size_t)gm * K + (k0 + c)] : 0.f;
        }
#pragma unroll
        for (int i = tid; i < BK * BN; i += 256) {
            int r = i / BN, c = i % BN;
            Bs[r][c] = W[(size_t)(k0 + r) * Nc + c];
        }
        __syncthreads();

#pragma unroll
        for (int kk = 0; kk < BK; ++kk) {
            float a[4], b[4];
#pragma unroll
            for (int i = 0; i < 4; ++i) a[i] = As[kk][ty * 4 + i];
#pragma unroll
            for (int j = 0; j < 4; ++j) b[j] = Bs[kk][tx * 4 + j];
#pragma unroll
            for (int i = 0; i < 4; ++i)
#pragma unroll
                for (int j = 0; j < 4; ++j) acc[i][j] += a[i] * b[j];
        }
        __syncthreads();
    }

#pragma unroll
    for (int i = 0; i < 4; ++i) {
        int gm = bm + ty * 4 + i;
        if (gm >= M) continue;
#pragma unroll
        for (int j = 0; j < 4; ++j) {
            int gn = tx * 4 + j;
            float v = fmaxf(acc[i][j], 0.f);
            C[(size_t)gm * Nc + gn] = __float2half(v);
        }
    }
}

// ---------------- fp16 wmma GEMM (fp16 outputs) -----------------------------
// out[M, 128-block sel] = A[M,K](fp16) @ Wp[K,384](fp16) + bias -> fp16
// CTA tile 128x128; blockIdx.y = sel (0:xl, 1:xr, 2:sk). K in {32, 128}.
#define A_LDH 72
#define B_LDH 136

__global__ __launch_bounds__(256, 2)
void gemm_h16_kernel(const __half* __restrict__ A, const __half* __restrict__ B,
                     const float* __restrict__ bias,
                     __half* __restrict__ xl, __half* __restrict__ xr,
                     __half* __restrict__ sk, int M, int K) {
    __shared__ __align__(16) __half As[128 * A_LDH];   // 128 x <=64
    __shared__ __align__(16) __half Bs[64 * B_LDH];    // <=64 x 128
    __shared__ float stage[8][16 * 20];

    const int tid = threadIdx.x;
    const int warp = tid >> 5;
    const int lane = tid & 31;
    const int wm = warp >> 1;     // 0..3: rows wm*32
    const int wn = warp & 1;      // 0..1: cols wn*64
    const int bm = blockIdx.x * 128;
    const int sel = blockIdx.y;   // 0,1,2
    const int bn = sel * 128;

    wmma::fragment<wmma::accumulator, 16, 16, 16, float> fc[2][4];
#pragma unroll
    for (int i = 0; i < 2; ++i)
#pragma unroll
        for (int j = 0; j < 4; ++j) wmma::fill_fragment(fc[i][j], 0.f);

    for (int k0 = 0; k0 < K; k0 += 64) {
        const int kw = min(64, K - k0);         // 64 or 32
        const int kv = kw >> 3;                 // uint4 per A row
        // A tile: 128 x kw
        for (int i = tid; i < 128 * kv; i += 256) {
            int r = i / kv, c = (i % kv) * 8;
            int gm = bm + r;
            uint4 v = make_uint4(0, 0, 0, 0);
            if (gm < M) v = *reinterpret_cast<const uint4*>(A + (size_t)gm * K + k0 + c);
            *reinterpret_cast<uint4*>(&As[r * A_LDH + c]) = v;
        }
        // B tile: kw x 128
        for (int i = tid; i < kw * 16; i += 256) {
            int r = i >> 4, c = (i & 15) * 8;
            uint4 v = *reinterpret_cast<const uint4*>(B + (size_t)(k0 + r) * 384 + bn + c);
            *reinterpret_cast<uint4*>(&Bs[r * B_LDH + c]) = v;
        }
        __syncthreads();

        for (int kk = 0; kk < kw; kk += 16) {
            wmma::fragment<wmma::matrix_a, 16, 16, 16, __half, wmma::row_major> fa[2];
            wmma::fragment<wmma::matrix_b, 16, 16, 16, __half, wmma::row_major> fb[4];
#pragma unroll
            for (int i = 0; i < 2; ++i)
                wmma::load_matrix_sync(fa[i], &As[(wm * 32 + i * 16) * A_LDH + kk], A_LDH);
#pragma unroll
            for (int j = 0; j < 4; ++j)
                wmma::load_matrix_sync(fb[j], &Bs[kk * B_LDH + wn * 64 + j * 16], B_LDH);
#pragma unroll
            for (int i = 0; i < 2; ++i)
#pragma unroll
                for (int j = 0; j < 4; ++j)
                    wmma::mma_sync(fc[i][j], fa[i], fb[j], fc[i][j]);
        }
        __syncthreads();
    }

    __half* outp = (sel == 0) ? xl : ((sel == 1) ? xr : sk);

#pragma unroll
    for (int i = 0; i < 2; ++i) {
#pragma unroll
        for (int j = 0; j < 4; ++j) {
            wmma::store_matrix_sync(&stage[warp][0], fc[i][j], 20, wmma::mem_row_major);
            __syncwarp();
            int r0 = bm + wm * 32 + i * 16;
            int c0 = wn * 64 + j * 16;        // local col in [0,128)
#pragma unroll
            for (int t = lane; t < 256; t += 32) {
                int lr = t >> 4, lc = t & 15;
                int gm = r0 + lr;
                if (gm < M)
                    outp[(size_t)gm * HCC + c0 + lc] =
                        __float2half(stage[warp][lr * 20 + lc] + __ldg(&bias[bn + c0 + lc]));
            }
            __syncwarp();
        }
    }
}

// ---------------- GAT edge kernel: warp per node, 8 lanes per head ---------
// lane = (head = lane>>3, 4 channels at (lane&7)*4). 3 shfl per edge score.
__global__ __launch_bounds__(256)
void gat_edge_kernel(const int* __restrict__ rowptr, const int* __restrict__ csr,
                     const __half* __restrict__ xl, const __half* __restrict__ xr,
                     const __half* __restrict__ sk,
                     const float* __restrict__ att, const float* __restrict__ cb,
                     __half* __restrict__ outh, float* __restrict__ outf, int n) {
    int warp_id = (blockIdx.x * blockDim.x + threadIdx.x) >> 5;
    if (warp_id >= n) return;
    const int lane = threadIdx.x & 31;
    const int node = warp_id;
    const int head = lane >> 3;
    const int chan = head * CC + (lane & 7) * 4;   // channel base in [0,128)

    float xrv[4], attv[4];
    {
        uint2 u = *reinterpret_cast<const uint2*>(xr + (size_t)node * HCC + chan);
        __half2 h0 = *reinterpret_cast<__half2*>(&u.x);
        __half2 h1 = *reinterpret_cast<__half2*>(&u.y);
        xrv[0] = __low2float(h0); xrv[1] = __high2float(h0);
        xrv[2] = __low2float(h1); xrv[3] = __high2float(h1);
        float4 a = *reinterpret_cast<const float4*>(att + chan);
        attv[0] = a.x; attv[1] = a.y; attv[2] = a.z; attv[3] = a.w;
    }

    float m = -INFINITY, den = 0.f;
    float acc[4] = {0.f, 0.f, 0.f, 0.f};

    const int e0 = rowptr[node], e1 = rowptr[node + 1];
    if (e0 < e1) {
        int src_n = __ldg(&csr[e0]);
        uint2 u_n = *reinterpret_cast<const uint2*>(xl + (size_t)src_n * HCC + chan);
        for (int e = e0; e < e1; ++e) {
            uint2 u = u_n;
            if (e + 1 < e1) {
                int sn = __ldg(&csr[e + 1]);
                u_n = *reinterpret_cast<const uint2*>(xl + (size_t)sn * HCC + chan);
            }
            __half2 h0 = *reinterpret_cast<__half2*>(&u.x);
            __half2 h1 = *reinterpret_cast<__half2*>(&u.y);
            float xlv[4] = {__low2float(h0), __high2float(h0),
                            __low2float(h1), __high2float(h1)};
            float s = 0.f;
#pragma unroll
            for (int j = 0; j < 4; ++j) {
                float t = xlv[j] + xrv[j];
                t = (t > 0.f) ? t : NEG_SLOPE * t;
                s = fmaf(t, attv[j], s);
            }
            // reduce over the 8 lanes of this head
            s += __shfl_xor_sync(0xffffffffu, s, 4);
            s += __shfl_xor_sync(0xffffffffu, s, 2);
            s += __shfl_xor_sync(0xffffffffu, s, 1);

            float nm = fmaxf(m, s);
            float scale = __expf(m - nm);
            float p = __expf(s - nm);
            den = den * scale + p;
#pragma unroll
            for (int j = 0; j < 4; ++j) acc[j] = fmaf(acc[j], scale, p * xlv[j]);
            m = nm;
        }
    }

    float inv_den = (den > 0.f) ? (1.f / den) : 0.f;
    float o[4];
    {
        uint2 u = *reinterpret_cast<const uint2*>(sk + (size_t)node * HCC + chan);
        __half2 h0 = *reinterpret_cast<__half2*>(&u.x);
        __half2 h1 = *reinterpret_cast<__half2*>(&u.y);
        float skv[4] = {__low2float(h0), __high2float(h0),
                        __low2float(h1), __high2float(h1)};
        float4 c = *reinterpret_cast<const float4*>(cb + chan);
        o[0] = acc[0] * inv_den + c.x + skv[0];
        o[1] = acc[1] * inv_den + c.y + skv[1];
        o[2] = acc[2] * inv_den + c.z + skv[2];
        o[3] = acc[3] * inv_den + c.w + skv[3];
    }

    if (outh) {
        // mid layer: relu -> fp16
        __half2 w0 = __floats2half2_rn(fmaxf(o[0], 0.f), fmaxf(o[1], 0.f));
        __half2 w1 = __floats2half2_rn(fmaxf(o[2], 0.f), fmaxf(o[3], 0.f));
        uint2 u;
        u.x = *reinterpret_cast<uint32_t*>(&w0);
        u.y = *reinterpret_cast<uint32_t*>(&w1);
        *reinterpret_cast<uint2*>(outh + (size_t)node * HCC + chan) = u;
    } else {
        // final layer: L2 normalize over all 128 channels -> fp32
        float sq = o[0] * o[0] + o[1] * o[1] + o[2] * o[2] + o[3] * o[3];
#pragma unroll
        for (int off = 16; off > 0; off >>= 1)
            sq += __shfl_xor_sync(0xffffffffu, sq, off);
        float inv = rsqrtf(sq);
        float4 w = make_float4(o[0] * inv, o[1] * inv, o[2] * inv, o[3] * inv);
        *reinterpret_cast<float4*>(outf + (size_t)node * HCC + chan) = w;
    }
}

// ---------------- host ------------------------------------------------------
extern "C" void kernel_launch(void* const* d_in, const int* in_sizes, int n_in,
                              void* d_out, int out_size) {
    const float* x  = (const float*)d_in[0];
    const int*   ei = (const int*)d_in[1];
    const float* W0 = (const float*)d_in[2];

    // f: 3..10, m: 11..18, l: 19..26 (order: Wl, bl, Wr, br, att, cb, Ws, bs)
    const float* P[27];
    for (int i = 3; i < 27; ++i) P[i] = (const float*)d_in[i];

    __half *hh, *xl, *xr, *sk, *Wf, *Wm, *Wl2;
    float *bf, *bm_, *bl2;
    int *deg, *rowptr, *cursor, *csr;
    cudaGetSymbolAddress((void**)&hh,     g_hh);
    cudaGetSymbolAddress((void**)&xl,     g_xl);
    cudaGetSymbolAddress((void**)&xr,     g_xr);
    cudaGetSymbolAddress((void**)&sk,     g_sk);
    cudaGetSymbolAddress((void**)&deg,    g_deg);
    cudaGetSymbolAddress((void**)&rowptr, g_rowptr);
    cudaGetSymbolAddress((void**)&cursor, g_cursor);
    cudaGetSymbolAddress((void**)&csr,    g_csr);
    cudaGetSymbolAddress((void**)&Wf,     g_Wf);
    cudaGetSymbolAddress((void**)&bf,     g_bf);
    cudaGetSymbolAddress((void**)&Wm,     g_Wm);
    cudaGetSymbolAddress((void**)&bm_,    g_bm);
    cudaGetSymbolAddress((void**)&Wl2,    g_Wl2);
    cudaGetSymbolAddress((void**)&bl2,    g_bl2);

    const int* src = ei;
    const int* dst = ei + EE;

    // ---- CSR build (by dst) ----
    zero_int_kernel<<<(NN + 255) / 256, 256>>>(deg, NN);
    hist_kernel<<<(EE + 255) / 256, 256>>>(dst, deg, EE);
    scan_kernel<<<1, 1024>>>(deg, rowptr, cursor, NN);
    scatter_kernel<<<(EE + 255) / 256, 256>>>(src, dst, cursor, csr, EE);

    // ---- pack per-layer weights to fp16 ----
    pack_h_kernel<<<(EMB * 128 + 255) / 256, 256>>>(P[3], P[5], P[9], P[4], P[6], P[10], Wf, bf, EMB);
    pack_h_kernel<<<(HCC * 128 + 255) / 256, 256>>>(P[11], P[13], P[17], P[12], P[14], P[18], Wm, bm_, HCC);
    pack_h_kernel<<<(HCC * 128 + 255) / 256, 256>>>(P[19], P[21], P[25], P[20], P[22], P[26], Wl2, bl2, HCC);

    // h0 = relu(x @ W0)  [N, 32] fp16
    gemm0_kernel<<<(NN + BM - 1) / BM, 256>>>(x, W0, hh, NN, F_IN, EMB);

    dim3 wgrid((NN + 127) / 128, 3);
    int edge_blocks = (NN * 32 + 255) / 256;

    auto run_layer = [&](const __half* Wp, const float* bp, int K,
                         const float* att, const float* cb,
                         __half* outh, float* outf) {
        gemm_h16_kernel<<<wgrid, 256>>>(hh, Wp, bp, xl, xr, sk, NN, K);
        gat_edge_kernel<<<edge_blocks, 256>>>(rowptr, csr, xl, xr, sk, att, cb,
                                              outh, outf, NN);
    };

    run_layer(Wf,  bf,  EMB, P[7],  P[8],  hh, nullptr);   // first GAT layer (K=32)
    run_layer(Wm,  bm_, HCC, P[15], P[16], hh, nullptr);   // mid x3 (shared weights)
    run_layer(Wm,  bm_, HCC, P[15], P[16], hh, nullptr);
    run_layer(Wm,  bm_, HCC, P[15], P[16], hh, nullptr);
    run_layer(Wl2, bl2, HCC, P[23], P[24], nullptr, (float*)d_out);  // last + L2 norm
}

// round 12
// speedup vs baseline: 3.2320x; 1.0844x over previous
#include <cuda_runtime.h>
#include <cuda_fp16.h>
#include <mma.h>
#include <math.h>
#include <stdint.h>

using namespace nvcuda;

// Problem constants (fixed shapes)
#define NN 100000
#define EE 1000000
#define F_IN 64
#define EMB 32
#define HH 4
#define CC 32
#define HCC 128
#define NEG_SLOPE 0.2f

// ---------------- scratch (device globals; no allocation allowed) ----------
__device__ __align__(16) __half g_hh[(size_t)NN * HCC];   // fp16 activations
__device__ __align__(16) __half g_xl[(size_t)NN * HCC];
__device__ __align__(16) __half g_xr[(size_t)NN * HCC];
__device__ __align__(16) __half g_sk[(size_t)NN * HCC];
__device__ int   g_deg[NN];
__device__ int   g_rowptr[NN + 1];
__device__ int   g_cursor[NN];
__device__ int   g_csr[EE];
// packed per-layer weights fp16: Wp[K, 384] = Wl | Wr | Ws ; biases fp32 [384]
__device__ __align__(16) __half g_Wf [EMB * 384];
__device__ float g_bf [384];
__device__ __align__(16) __half g_Wm [HCC * 384];
__device__ float g_bm [384];
__device__ __align__(16) __half g_Wl2[HCC * 384];
__device__ float g_bl2[384];

// ---------------- small utility kernels -----------------------------------
__global__ void zero_int_kernel(int* p, int n) {
    int i = blockIdx.x * blockDim.x + threadIdx.x;
    if (i < n) p[i] = 0;
}

__global__ void hist_kernel(const int* __restrict__ dst, int* __restrict__ deg, int e) {
    int i = blockIdx.x * blockDim.x + threadIdx.x;
    if (i < e) atomicAdd(&deg[dst[i]], 1);
}

__global__ void scan_kernel(const int* __restrict__ deg, int* __restrict__ rowptr,
                            int* __restrict__ cursor, int n) {
    __shared__ int sums[1024];
    int tid = threadIdx.x;
    int chunk = (n + 1023) / 1024;
    int start = tid * chunk;
    int end   = min(start + chunk, n);
    int s = 0;
    for (int i = start; i < end; ++i) s += deg[i];
    sums[tid] = s;
    __syncthreads();
    for (int off = 1; off < 1024; off <<= 1) {
        int v = 0;
        if (tid >= off) v = sums[tid - off];
        __syncthreads();
        if (tid >= off) sums[tid] += v;
        __syncthreads();
    }
    int prefix = (tid == 0) ? 0 : sums[tid - 1];
    for (int i = start; i < end; ++i) {
        rowptr[i] = prefix;
        cursor[i] = prefix;
        prefix += deg[i];
    }
    if (tid == 1023) rowptr[n] = sums[1023];
}

__global__ void scatter_kernel(const int* __restrict__ src, const int* __restrict__ dst,
                               int* __restrict__ cursor, int* __restrict__ csr, int e) {
    int i = blockIdx.x * blockDim.x + threadIdx.x;
    if (i < e) {
        int d = dst[i];
        int pos = atomicAdd(&cursor[d], 1);
        csr[pos] = src[i];
    }
}

// pack Wl|Wr|Ws (each [K,128] row-major fp32) -> fp16 Wp [K,384]; biases fp32
__global__ void pack_h_kernel(const float* __restrict__ Wl, const float* __restrict__ Wr,
                              const float* __restrict__ Ws,
                              const float* __restrict__ bl, const float* __restrict__ br,
                              const float* __restrict__ bs,
                              __half* __restrict__ Wp, float* __restrict__ bp, int K) {
    int i = blockIdx.x * blockDim.x + threadIdx.x;
    int total = K * 128;
    if (i < total) {
        int k = i / 128, c = i % 128;
        Wp[(size_t)k * 384 + c]       = __float2half(Wl[i]);
        Wp[(size_t)k * 384 + 128 + c] = __float2half(Wr[i]);
        Wp[(size_t)k * 384 + 256 + c] = __float2half(Ws[i]);
    }
    if (i < 128) {
        bp[i]       = bl[i];
        bp[128 + i] = br[i];
        bp[256 + i] = bs[i];
    }
}

// ---------------- plain SGEMM for x @ W0 -> relu -> fp16 h0 ----------------
#define BM 128
#define BN 32
#define BK 16

__global__ __launch_bounds__(256, 2)
void gemm0_kernel(const float* __restrict__ A, const float* __restrict__ W,
                  __half* __restrict__ C, int M, int K, int Nc) {
    __shared__ float As[BK][BM + 4];
    __shared__ float Bs[BK][BN];

    int bm = blockIdx.x * BM;
    int tid = threadIdx.x;
    int tx = tid & 7;
    int ty = tid >> 3;

    float acc[4][4];
#pragma unroll
    for (int i = 0; i < 4; ++i)
#pragma unroll
        for (int j = 0; j < 4; ++j) acc[i][j] = 0.f;

    for (int k0 = 0; k0 < K; k0 += BK) {
#pragma unroll
        for (int i = tid; i < BM * BK; i += 256) {
            int r = i / BK, c = i % BK;
            int gm = bm + r;
            As[c][r] = (gm < M) ? A[(size_t)gm * K + (k0 + c)] : 0.f;
        }
#pragma unroll
        for (int i = tid; i < BK * BN; i += 256) {
            int r = i / BN, c = i % BN;
            Bs[r][c] = W[(size_t)(k0 + r) * Nc + c];
        }
        __syncthreads();

#pragma unroll
        for (int kk = 0; kk < BK; ++kk) {
            float a[4], b[4];
#pragma unroll
            for (int i = 0; i < 4; ++i) a[i] = As[kk][ty * 4 + i];
#pragma unroll
            for (int j = 0; j < 4; ++j) b[j] = Bs[kk][tx * 4 + j];
#pragma unroll
            for (int i = 0; i < 4; ++i)
#pragma unroll
                for (int j = 0; j < 4; ++j) acc[i][j] += a[i] * b[j];
        }
        __syncthreads();
    }

#pragma unroll
    for (int i = 0; i < 4; ++i) {
        int gm = bm + ty * 4 + i;
        if (gm >= M) continue;
#pragma unroll
        for (int j = 0; j < 4; ++j) {
            int gn = tx * 4 + j;
            float v = fmaxf(acc[i][j], 0.f);
            C[(size_t)gm * Nc + gn] = __float2half(v);
        }
    }
}

// ---------------- fused fp16 wmma GEMM: A staged once, 3 outputs -----------
// For sel 0..2: out_sel[M,128] = A[M,K] @ Wp[K, sel*128 : +128] + bias
// CTA: 128 rows; dynamic smem: As 128xK (LD 136), Bs Kx128 (LD 136), stage.
#define A_LDF 136
#define B_LDF 136
#define SM_AS   0
#define SM_BS   34816
#define SM_STG  69632
#define SM_TOTAL (69632 + 10240)

__global__ __launch_bounds__(256, 2)
void gemm_h16_fused(const __half* __restrict__ A, const __half* __restrict__ B,
                    const float* __restrict__ bias,
                    __half* __restrict__ xl, __half* __restrict__ xr,
                    __half* __restrict__ sk, int M, int K) {
    extern __shared__ __align__(16) char dynbuf[];
    __half* As = reinterpret_cast<__half*>(dynbuf + SM_AS);
    __half* Bs = reinterpret_cast<__half*>(dynbuf + SM_BS);
    float*  stg = reinterpret_cast<float*>(dynbuf + SM_STG);

    const int tid = threadIdx.x;
    const int warp = tid >> 5;
    const int lane = tid & 31;
    const int wm = warp >> 1;     // 0..3: rows wm*32
    const int wn = warp & 1;      // 0..1: cols wn*64
    const int bm = blockIdx.x * 128;

    // stage A once: 128 x K
    const int kv = K >> 3;        // uint4 per row
    for (int i = tid; i < 128 * kv; i += 256) {
        int r = i / kv, c = (i % kv) * 8;
        int gm = bm + r;
        uint4 v = make_uint4(0, 0, 0, 0);
        if (gm < M) v = *reinterpret_cast<const uint4*>(A + (size_t)gm * K + c);
        *reinterpret_cast<uint4*>(&As[r * A_LDF + c]) = v;
    }
    __syncthreads();

    float* stage = stg + warp * 320;

    for (int sel = 0; sel < 3; ++sel) {
        // stage B: K x 128 for this sel
        for (int i = tid; i < K * 16; i += 256) {
            int r = i >> 4, c = (i & 15) * 8;
            uint4 v = *reinterpret_cast<const uint4*>(B + (size_t)r * 384 + sel * 128 + c);
            *reinterpret_cast<uint4*>(&Bs[r * B_LDF + c]) = v;
        }
        __syncthreads();

        wmma::fragment<wmma::accumulator, 16, 16, 16, float> fc[2][4];
#pragma unroll
        for (int i = 0; i < 2; ++i)
#pragma unroll
            for (int j = 0; j < 4; ++j) wmma::fill_fragment(fc[i][j], 0.f);

        for (int kk = 0; kk < K; kk += 16) {
            wmma::fragment<wmma::matrix_a, 16, 16, 16, __half, wmma::row_major> fa[2];
            wmma::fragment<wmma::matrix_b, 16, 16, 16, __half, wmma::row_major> fb[4];
#pragma unroll
            for (int i = 0; i < 2; ++i)
                wmma::load_matrix_sync(fa[i], &As[(wm * 32 + i * 16) * A_LDF + kk], A_LDF);
#pragma unroll
            for (int j = 0; j < 4; ++j)
                wmma::load_matrix_sync(fb[j], &Bs[kk * B_LDF + wn * 64 + j * 16], B_LDF);
#pragma unroll
            for (int i = 0; i < 2; ++i)
#pragma unroll
                for (int j = 0; j < 4; ++j)
                    wmma::mma_sync(fc[i][j], fa[i], fb[j], fc[i][j]);
        }

        __half* outp = (sel == 0) ? xl : ((sel == 1) ? xr : sk);

#pragma unroll
        for (int i = 0; i < 2; ++i) {
#pragma unroll
            for (int j = 0; j < 4; ++j) {
                wmma::store_matrix_sync(stage, fc[i][j], 20, wmma::mem_row_major);
                __syncwarp();
                int r0 = bm + wm * 32 + i * 16;
                int c0 = wn * 64 + j * 16;        // local col in [0,128)
#pragma unroll
                for (int t = lane; t < 256; t += 32) {
                    int lr = t >> 4, lc = t & 15;
                    int gm = r0 + lr;
                    if (gm < M)
                        outp[(size_t)gm * HCC + c0 + lc] =
                            __float2half(stage[lr * 20 + lc] +
                                         __ldg(&bias[sel * 128 + c0 + lc]));
                }
                __syncwarp();
            }
        }
        __syncthreads();   // all warps done with Bs before next sel reloads it
    }
}

// ---------------- GAT edge kernel: warp per node, 8 lanes per head ---------
// lane = (head = lane>>3, 4 channels at (lane&7)*4). 2-edge batched updates.
__global__ __launch_bounds__(256)
void gat_edge_kernel(const int* __restrict__ rowptr, const int* __restrict__ csr,
                     const __half* __restrict__ xl, const __half* __restrict__ xr,
                     const __half* __restrict__ sk,
                     const float* __restrict__ att, const float* __restrict__ cb,
                     __half* __restrict__ outh, float* __restrict__ outf, int n) {
    int warp_id = (blockIdx.x * blockDim.x + threadIdx.x) >> 5;
    if (warp_id >= n) return;
    const int lane = threadIdx.x & 31;
    const int node = warp_id;
    const int head = lane >> 3;
    const int chan = head * CC + (lane & 7) * 4;   // channel base in [0,128)

    float xrv[4], attv[4];
    {
        uint2 u = *reinterpret_cast<const uint2*>(xr + (size_t)node * HCC + chan);
        __half2 h0 = *reinterpret_cast<__half2*>(&u.x);
        __half2 h1 = *reinterpret_cast<__half2*>(&u.y);
        xrv[0] = __low2float(h0); xrv[1] = __high2float(h0);
        xrv[2] = __low2float(h1); xrv[3] = __high2float(h1);
        float4 a = *reinterpret_cast<const float4*>(att + chan);
        attv[0] = a.x; attv[1] = a.y; attv[2] = a.z; attv[3] = a.w;
    }

    float m = -INFINITY, den = 0.f;
    float acc[4] = {0.f, 0.f, 0.f, 0.f};

    const int e0 = rowptr[node], e1 = rowptr[node + 1];
    int rem = e1 - e0;
    int e = e0;
    uint2 u0 = make_uint2(0, 0), u1 = make_uint2(0, 0);
    if (rem > 0) {
        int s = __ldg(&csr[e]);
        u0 = *reinterpret_cast<const uint2*>(xl + (size_t)s * HCC + chan);
    }
    if (rem > 1) {
        int s = __ldg(&csr[e + 1]);
        u1 = *reinterpret_cast<const uint2*>(xl + (size_t)s * HCC + chan);
    }

    while (rem >= 2) {
        uint2 a = u0, b = u1;
        if (rem > 2) {
            int s = __ldg(&csr[e + 2]);
            u0 = *reinterpret_cast<const uint2*>(xl + (size_t)s * HCC + chan);
        }
        if (rem > 3) {
            int s = __ldg(&csr[e + 3]);
            u1 = *reinterpret_cast<const uint2*>(xl + (size_t)s * HCC + chan);
        }
        __half2 a0 = *reinterpret_cast<__half2*>(&a.x);
        __half2 a1 = *reinterpret_cast<__half2*>(&a.y);
        __half2 b0 = *reinterpret_cast<__half2*>(&b.x);
        __half2 b1 = *reinterpret_cast<__half2*>(&b.y);
        float xla[4] = {__low2float(a0), __high2float(a0),
                        __low2float(a1), __high2float(a1)};
        float xlb[4] = {__low2float(b0), __high2float(b0),
                        __low2float(b1), __high2float(b1)};
        float sa = 0.f, sb = 0.f;
#pragma unroll
        for (int j = 0; j < 4; ++j) {
            float ta = xla[j] + xrv[j];
            ta = (ta > 0.f) ? ta : NEG_SLOPE * ta;
            sa = fmaf(ta, attv[j], sa);
            float tb = xlb[j] + xrv[j];
            tb = (tb > 0.f) ? tb : NEG_SLOPE * tb;
            sb = fmaf(tb, attv[j], sb);
        }
        sa += __shfl_xor_sync(0xffffffffu, sa, 4);
        sb += __shfl_xor_sync(0xffffffffu, sb, 4);
        sa += __shfl_xor_sync(0xffffffffu, sa, 2);
        sb += __shfl_xor_sync(0xffffffffu, sb, 2);
        sa += __shfl_xor_sync(0xffffffffu, sa, 1);
        sb += __shfl_xor_sync(0xffffffffu, sb, 1);

        // batched online-softmax update (exact)
        float nm = fmaxf(m, fmaxf(sa, sb));
        float scale = __expf(m - nm);
        float pa = __expf(sa - nm);
        float pb = __expf(sb - nm);
        den = den * scale + pa + pb;
#pragma unroll
        for (int j = 0; j < 4; ++j)
            acc[j] = fmaf(acc[j], scale, fmaf(pa, xla[j], pb * xlb[j]));
        m = nm;
        e += 2; rem -= 2;
    }
    if (rem == 1) {
        __half2 a0 = *reinterpret_cast<__half2*>(&u0.x);
        __half2 a1 = *reinterpret_cast<__half2*>(&u0.y);
        float xla[4] = {__low2float(a0), __high2float(a0),
                        __low2float(a1), __high2float(a1)};
        float sa = 0.f;
#pragma unroll
        for (int j = 0; j < 4; ++j) {
            float t = xla[j] + xrv[j];
            t = (t > 0.f) ? t : NEG_SLOPE * t;
            sa = fmaf(t, attv[j], sa);
        }
        sa += __shfl_xor_sync(0xffffffffu, sa, 4);
        sa += __shfl_xor_sync(0xffffffffu, sa, 2);
        sa += __shfl_xor_sync(0xffffffffu, sa, 1);
        float nm = fmaxf(m, sa);
        float scale = __expf(m - nm);
        float p = __expf(sa - nm);
        den = den * scale + p;
#pragma unroll
        for (int j = 0; j < 4; ++j)
            acc[j] = fmaf(acc[j], scale, p * xla[j]);
        m = nm;
    }

    float inv_den = (den > 0.f) ? (1.f / den) : 0.f;
    float o[4];
    {
        uint2 u = *reinterpret_cast<const uint2*>(sk + (size_t)node * HCC + chan);
        __half2 h0 = *reinterpret_cast<__half2*>(&u.x);
        __half2 h1 = *reinterpret_cast<__half2*>(&u.y);
        float skv[4] = {__low2float(h0), __high2float(h0),
                        __low2float(h1), __high2float(h1)};
        float4 c = *reinterpret_cast<const float4*>(cb + chan);
        o[0] = acc[0] * inv_den + c.x + skv[0];
        o[1] = acc[1] * inv_den + c.y + skv[1];
        o[2] = acc[2] * inv_den + c.z + skv[2];
        o[3] = acc[3] * inv_den + c.w + skv[3];
    }

    if (outh) {
        __half2 w0 = __floats2half2_rn(fmaxf(o[0], 0.f), fmaxf(o[1], 0.f));
        __half2 w1 = __floats2half2_rn(fmaxf(o[2], 0.f), fmaxf(o[3], 0.f));
        uint2 u;
        u.x = *reinterpret_cast<uint32_t*>(&w0);
        u.y = *reinterpret_cast<uint32_t*>(&w1);
        *reinterpret_cast<uint2*>(outh + (size_t)node * HCC + chan) = u;
    } else {
        float sq = o[0] * o[0] + o[1] * o[1] + o[2] * o[2] + o[3] * o[3];
#pragma unroll
        for (int off = 16; off > 0; off >>= 1)
            sq += __shfl_xor_sync(0xffffffffu, sq, off);
        float inv = rsqrtf(sq);
        float4 w = make_float4(o[0] * inv, o[1] * inv, o[2] * inv, o[3] * inv);
        *reinterpret_cast<float4*>(outf + (size_t)node * HCC + chan) = w;
    }
}

// ---------------- host ------------------------------------------------------
extern "C" void kernel_launch(void* const* d_in, const int* in_sizes, int n_in,
                              void* d_out, int out_size) {
    const float* x  = (const float*)d_in[0];
    const int*   ei = (const int*)d_in[1];
    const float* W0 = (const float*)d_in[2];

    // f: 3..10, m: 11..18, l: 19..26 (order: Wl, bl, Wr, br, att, cb, Ws, bs)
    const float* P[27];
    for (int i = 3; i < 27; ++i) P[i] = (const float*)d_in[i];

    __half *hh, *xl, *xr, *sk, *Wf, *Wm, *Wl2;
    float *bf, *bm_, *bl2;
    int *deg, *rowptr, *cursor, *csr;
    cudaGetSymbolAddress((void**)&hh,     g_hh);
    cudaGetSymbolAddress((void**)&xl,     g_xl);
    cudaGetSymbolAddress((void**)&xr,     g_xr);
    cudaGetSymbolAddress((void**)&sk,     g_sk);
    cudaGetSymbolAddress((void**)&deg,    g_deg);
    cudaGetSymbolAddress((void**)&rowptr, g_rowptr);
    cudaGetSymbolAddress((void**)&cursor, g_cursor);
    cudaGetSymbolAddress((void**)&csr,    g_csr);
    cudaGetSymbolAddress((void**)&Wf,     g_Wf);
    cudaGetSymbolAddress((void**)&bf,     g_bf);
    cudaGetSymbolAddress((void**)&Wm,     g_Wm);
    cudaGetSymbolAddress((void**)&bm_,    g_bm);
    cudaGetSymbolAddress((void**)&Wl2,    g_Wl2);
    cudaGetSymbolAddress((void**)&bl2,    g_bl2);

    static int smem_set = 0;
    if (!smem_set) {
        cudaFuncSetAttribute(gemm_h16_fused,
                             cudaFuncAttributeMaxDynamicSharedMemorySize, SM_TOTAL);
        smem_set = 1;
    }

    const int* src = ei;
    const int* dst = ei + EE;

    // ---- CSR build (by dst) ----
    zero_int_kernel<<<(NN + 255) / 256, 256>>>(deg, NN);
    hist_kernel<<<(EE + 255) / 256, 256>>>(dst, deg, EE);
    scan_kernel<<<1, 1024>>>(deg, rowptr, cursor, NN);
    scatter_kernel<<<(EE + 255) / 256, 256>>>(src, dst, cursor, csr, EE);

    // ---- pack per-layer weights to fp16 ----
    pack_h_kernel<<<(EMB * 128 + 255) / 256, 256>>>(P[3], P[5], P[9], P[4], P[6], P[10], Wf, bf, EMB);
    pack_h_kernel<<<(HCC * 128 + 255) / 256, 256>>>(P[11], P[13], P[17], P[12], P[14], P[18], Wm, bm_, HCC);
    pack_h_kernel<<<(HCC * 128 + 255) / 256, 256>>>(P[19], P[21], P[25], P[20], P[22], P[26], Wl2, bl2, HCC);

    // h0 = relu(x @ W0)  [N, 32] fp16
    gemm0_kernel<<<(NN + BM - 1) / BM, 256>>>(x, W0, hh, NN, F_IN, EMB);

    int gemm_blocks = (NN + 127) / 128;
    int edge_blocks = (NN * 32 + 255) / 256;

    auto run_layer = [&](const __half* Wp, const float* bp, int K,
                         const float* att, const float* cb,
                         __half* outh, float* outf) {
        gemm_h16_fused<<<gemm_blocks, 256, SM_TOTAL>>>(hh, Wp, bp, xl, xr, sk, NN, K);
        gat_edge_kernel<<<edge_blocks, 256>>>(rowptr, csr, xl, xr, sk, att, cb,
                                              outh, outf, NN);
    };

    run_layer(Wf,  bf,  EMB, P[7],  P[8],  hh, nullptr);   // first GAT layer (K=32)
    run_layer(Wm,  bm_, HCC, P[15], P[16], hh, nullptr);   // mid x3 (shared weights)
    run_layer(Wm,  bm_, HCC, P[15], P[16], hh, nullptr);
    run_layer(Wm,  bm_, HCC, P[15], P[16], hh, nullptr);
    run_layer(Wl2, bl2, HCC, P[23], P[24], nullptr, (float*)d_out);  // last + L2 norm
}

// round 14
// speedup vs baseline: 3.2433x; 1.0035x over previous
#include <cuda_runtime.h>
#include <cuda_fp16.h>
#include <mma.h>
#include <math.h>
#include <stdint.h>

using namespace nvcuda;

// Problem constants (fixed shapes)
#define NN 100000
#define EE 1000000
#define F_IN 64
#define EMB 32
#define HH 4
#define CC 32
#define HCC 128
#define NEG_SLOPE 0.2f

// ---------------- scratch (device globals; no allocation allowed) ----------
__device__ __align__(16) __half g_hh[(size_t)NN * HCC];   // fp16 activations
__device__ __align__(16) __half g_xl[(size_t)NN * HCC];
__device__ __align__(16) __half g_xr[(size_t)NN * HCC];
__device__ __align__(16) __half g_sk[(size_t)NN * HCC];
__device__ int   g_deg[NN];
__device__ int   g_rowptr[NN + 1];
__device__ int   g_cursor[NN];
__device__ int   g_csr[EE];
// packed per-layer weights fp16: Wp[K, 384] = Wl | Wr | Ws ; biases fp32 [384]
__device__ __align__(16) __half g_Wf [EMB * 384];
__device__ float g_bf [384];
__device__ __align__(16) __half g_Wm [HCC * 384];
__device__ float g_bm [384];
__device__ __align__(16) __half g_Wl2[HCC * 384];
__device__ float g_bl2[384];

// ---------------- small utility kernels -----------------------------------
__global__ void zero_int_kernel(int* p, int n) {
    int i = blockIdx.x * blockDim.x + threadIdx.x;
    if (i < n) p[i] = 0;
}

__global__ void hist_kernel(const int* __restrict__ dst, int* __restrict__ deg, int e) {
    int i = blockIdx.x * blockDim.x + threadIdx.x;
    if (i < e) atomicAdd(&deg[dst[i]], 1);
}

__global__ void scan_kernel(const int* __restrict__ deg, int* __restrict__ rowptr,
                            int* __restrict__ cursor, int n) {
    __shared__ int sums[1024];
    int tid = threadIdx.x;
    int chunk = (n + 1023) / 1024;
    int start = tid * chunk;
    int end   = min(start + chunk, n);
    int s = 0;
    for (int i = start; i < end; ++i) s += deg[i];
    sums[tid] = s;
    __syncthreads();
    for (int off = 1; off < 1024; off <<= 1) {
        int v = 0;
        if (tid >= off) v = sums[tid - off];
        __syncthreads();
        if (tid >= off) sums[tid] += v;
        __syncthreads();
    }
    int prefix = (tid == 0) ? 0 : sums[tid - 1];
    for (int i = start; i < end; ++i) {
        rowptr[i] = prefix;
        cursor[i] = prefix;
        prefix += deg[i];
    }
    if (tid == 1023) rowptr[n] = sums[1023];
}

__global__ void scatter_kernel(const int* __restrict__ src, const int* __restrict__ dst,
                               int* __restrict__ cursor, int* __restrict__ csr, int e) {
    int i = blockIdx.x * blockDim.x + threadIdx.x;
    if (i < e) {
        int d = dst[i];
        int pos = atomicAdd(&cursor[d], 1);
        csr[pos] = src[i];
    }
}

// pack Wl|Wr|Ws (each [K,128] row-major fp32) -> fp16 Wp [K,384]; biases fp32
__global__ void pack_h_kernel(const float* __restrict__ Wl, const float* __restrict__ Wr,
                              const float* __restrict__ Ws,
                              const float* __restrict__ bl, const float* __restrict__ br,
                              const float* __restrict__ bs,
                              __half* __restrict__ Wp, float* __restrict__ bp, int K) {
    int i = blockIdx.x * blockDim.x + threadIdx.x;
    int total = K * 128;
    if (i < total) {
        int k = i / 128, c = i % 128;
        Wp[(size_t)k * 384 + c]       = __float2half(Wl[i]);
        Wp[(size_t)k * 384 + 128 + c] = __float2half(Wr[i]);
        Wp[(size_t)k * 384 + 256 + c] = __float2half(Ws[i]);
    }
    if (i < 128) {
        bp[i]       = bl[i];
        bp[128 + i] = br[i];
        bp[256 + i] = bs[i];
    }
}

// ---------------- plain SGEMM for x @ W0 -> relu -> fp16 h0 ----------------
#define BM 128
#define BN 32
#define BK 16

__global__ __launch_bounds__(256, 2)
void gemm0_kernel(const float* __restrict__ A, const float* __restrict__ W,
                  __half* __restrict__ C, int M, int K, int Nc) {
    __shared__ float As[BK][BM + 4];
    __shared__ float Bs[BK][BN];

    int bm = blockIdx.x * BM;
    int tid = threadIdx.x;
    int tx = tid & 7;
    int ty = tid >> 3;

    float acc[4][4];
#pragma unroll
    for (int i = 0; i < 4; ++i)
#pragma unroll
        for (int j = 0; j < 4; ++j) acc[i][j] = 0.f;

    for (int k0 = 0; k0 < K; k0 += BK) {
#pragma unroll
        for (int i = tid; i < BM * BK; i += 256) {
            int r = i / BK, c = i % BK;
            int gm = bm + r;
            As[c][r] = (gm < M) ? A[(size_t)gm * K + (k0 + c)] : 0.f;
        }
#pragma unroll
        for (int i = tid; i < BK * BN; i += 256) {
            int r = i / BN, c = i % BN;
            Bs[r][c] = W[(size_t)(k0 + r) * Nc + c];
        }
        __syncthreads();

#pragma unroll
        for (int kk = 0; kk < BK; ++kk) {
            float a[4], b[4];
#pragma unroll
            for (int i = 0; i < 4; ++i) a[i] = As[kk][ty * 4 + i];
#pragma unroll
            for (int j = 0; j < 4; ++j) b[j] = Bs[kk][tx * 4 + j];
#pragma unroll
            for (int i = 0; i < 4; ++i)
#pragma unroll
                for (int j = 0; j < 4; ++j) acc[i][j] += a[i] * b[j];
        }
        __syncthreads();
    }

#pragma unroll
    for (int i = 0; i < 4; ++i) {
        int gm = bm + ty * 4 + i;
        if (gm >= M) continue;
        // vectorized: 4 halves = one uint2
        __half2 w0 = __floats2half2_rn(fmaxf(acc[i][0], 0.f), fmaxf(acc[i][1], 0.f));
        __half2 w1 = __floats2half2_rn(fmaxf(acc[i][2], 0.f), fmaxf(acc[i][3], 0.f));
        uint2 u;
        u.x = *reinterpret_cast<uint32_t*>(&w0);
        u.y = *reinterpret_cast<uint32_t*>(&w1);
        *reinterpret_cast<uint2*>(C + (size_t)gm * Nc + tx * 4) = u;
    }
}

// ---------------- fused fp16 wmma GEMM: A staged once, 3 outputs -----------
// For sel 0..2: out_sel[M,128] = A[M,K] @ Wp[K, sel*128 : +128] + bias
// CTA: 128 rows; dynamic smem: As 128xK (LD 136), Bs Kx128 (LD 136), stage.
#define A_LDF 136
#define B_LDF 136
#define SM_AS   0
#define SM_BS   34816
#define SM_STG  69632
#define SM_TOTAL (69632 + 10240)

__global__ __launch_bounds__(256, 2)
void gemm_h16_fused(const __half* __restrict__ A, const __half* __restrict__ B,
                    const float* __restrict__ bias,
                    __half* __restrict__ xl, __half* __restrict__ xr,
                    __half* __restrict__ sk, int M, int K) {
    extern __shared__ __align__(16) char dynbuf[];
    __half* As = reinterpret_cast<__half*>(dynbuf + SM_AS);
    __half* Bs = reinterpret_cast<__half*>(dynbuf + SM_BS);
    float*  stg = reinterpret_cast<float*>(dynbuf + SM_STG);

    const int tid = threadIdx.x;
    const int warp = tid >> 5;
    const int lane = tid & 31;
    const int wm = warp >> 1;     // 0..3: rows wm*32
    const int wn = warp & 1;      // 0..1: cols wn*64
    const int bm = blockIdx.x * 128;

    // stage A once: 128 x K
    const int kv = K >> 3;        // uint4 per row
    for (int i = tid; i < 128 * kv; i += 256) {
        int r = i / kv, c = (i % kv) * 8;
        int gm = bm + r;
        uint4 v = make_uint4(0, 0, 0, 0);
        if (gm < M) v = *reinterpret_cast<const uint4*>(A + (size_t)gm * K + c);
        *reinterpret_cast<uint4*>(&As[r * A_LDF + c]) = v;
    }
    __syncthreads();

    float* stage = stg + warp * 320;   // 16 rows x 20 floats per warp

    for (int sel = 0; sel < 3; ++sel) {
        // stage B: K x 128 for this sel
        for (int i = tid; i < K * 16; i += 256) {
            int r = i >> 4, c = (i & 15) * 8;
            uint4 v = *reinterpret_cast<const uint4*>(B + (size_t)r * 384 + sel * 128 + c);
            *reinterpret_cast<uint4*>(&Bs[r * B_LDF + c]) = v;
        }
        __syncthreads();

        wmma::fragment<wmma::accumulator, 16, 16, 16, float> fc[2][4];
#pragma unroll
        for (int i = 0; i < 2; ++i)
#pragma unroll
            for (int j = 0; j < 4; ++j) wmma::fill_fragment(fc[i][j], 0.f);

        for (int kk = 0; kk < K; kk += 16) {
            wmma::fragment<wmma::matrix_a, 16, 16, 16, __half, wmma::row_major> fa[2];
            wmma::fragment<wmma::matrix_b, 16, 16, 16, __half, wmma::row_major> fb[4];
#pragma unroll
            for (int i = 0; i < 2; ++i)
                wmma::load_matrix_sync(fa[i], &As[(wm * 32 + i * 16) * A_LDF + kk], A_LDF);
#pragma unroll
            for (int j = 0; j < 4; ++j)
                wmma::load_matrix_sync(fb[j], &Bs[kk * B_LDF + wn * 64 + j * 16], B_LDF);
#pragma unroll
            for (int i = 0; i < 2; ++i)
#pragma unroll
                for (int j = 0; j < 4; ++j)
                    wmma::mma_sync(fc[i][j], fa[i], fb[j], fc[i][j]);
        }

        __half* outp = (sel == 0) ? xl : ((sel == 1) ? xr : sk);

        // epilogue: per fragment, stage fp32 then ONE uint4 (8 halves) store/lane
        const int lr = lane >> 1;            // 0..15: fragment row
        const int lc = (lane & 1) * 8;       // 0 or 8: fragment col base
#pragma unroll
        for (int i = 0; i < 2; ++i) {
#pragma unroll
            for (int j = 0; j < 4; ++j) {
                wmma::store_matrix_sync(stage, fc[i][j], 20, wmma::mem_row_major);
                __syncwarp();
                int gm = bm + wm * 32 + i * 16 + lr;
                int c0 = wn * 64 + j * 16 + lc;       // local col in [0,128)
                if (gm < M) {
                    const float* sp = stage + lr * 20 + lc;
                    float4 v0 = *reinterpret_cast<const float4*>(sp);
                    float4 v1 = *reinterpret_cast<const float4*>(sp + 4);
                    float4 b0 = *reinterpret_cast<const float4*>(bias + sel * 128 + c0);
                    float4 b1 = *reinterpret_cast<const float4*>(bias + sel * 128 + c0 + 4);
                    __half2 h0 = __floats2half2_rn(v0.x + b0.x, v0.y + b0.y);
                    __half2 h1 = __floats2half2_rn(v0.z + b0.z, v0.w + b0.w);
                    __half2 h2 = __floats2half2_rn(v1.x + b1.x, v1.y + b1.y);
                    __half2 h3 = __floats2half2_rn(v1.z + b1.z, v1.w + b1.w);
                    uint4 u;
                    u.x = *reinterpret_cast<uint32_t*>(&h0);
                    u.y = *reinterpret_cast<uint32_t*>(&h1);
                    u.z = *reinterpret_cast<uint32_t*>(&h2);
                    u.w = *reinterpret_cast<uint32_t*>(&h3);
                    *reinterpret_cast<uint4*>(outp + (size_t)gm * HCC + c0) = u;
                }
                __syncwarp();
            }
        }
        __syncthreads();   // all warps done with Bs before next sel reloads it
    }
}

// ---------------- GAT edge kernel: warp per node, 8 lanes per head ---------
// lane = (head = lane>>3, 4 channels at (lane&7)*4). 2-edge batched updates.
__global__ __launch_bounds__(256)
void gat_edge_kernel(const int* __restrict__ rowptr, const int* __restrict__ csr,
                     const __half* __restrict__ xl, const __half* __restrict__ xr,
                     const __half* __restrict__ sk,
                     const float* __restrict__ att, const float* __restrict__ cb,
                     __half* __restrict__ outh, float* __restrict__ outf, int n) {
    int warp_id = (blockIdx.x * blockDim.x + threadIdx.x) >> 5;
    if (warp_id >= n) return;
    const int lane = threadIdx.x & 31;
    const int node = warp_id;
    const int head = lane >> 3;
    const int chan = head * CC + (lane & 7) * 4;   // channel base in [0,128)

    float xrv[4], attv[4];
    {
        uint2 u = *reinterpret_cast<const uint2*>(xr + (size_t)node * HCC + chan);
        __half2 h0 = *reinterpret_cast<__half2*>(&u.x);
        __half2 h1 = *reinterpret_cast<__half2*>(&u.y);
        xrv[0] = __low2float(h0); xrv[1] = __high2float(h0);
        xrv[2] = __low2float(h1); xrv[3] = __high2float(h1);
        float4 a = *reinterpret_cast<const float4*>(att + chan);
        attv[0] = a.x; attv[1] = a.y; attv[2] = a.z; attv[3] = a.w;
    }

    float m = -INFINITY, den = 0.f;
    float acc[4] = {0.f, 0.f, 0.f, 0.f};

    const int e0 = rowptr[node], e1 = rowptr[node + 1];
    int rem = e1 - e0;
    int e = e0;
    uint2 u0 = make_uint2(0, 0), u1 = make_uint2(0, 0);
    if (rem > 0) {
        int s = __ldg(&csr[e]);
        u0 = *reinterpret_cast<const uint2*>(xl + (size_t)s * HCC + chan);
    }
    if (rem > 1) {
        int s = __ldg(&csr[e + 1]);
        u1 = *reinterpret_cast<const uint2*>(xl + (size_t)s * HCC + chan);
    }

    while (rem >= 2) {
        uint2 a = u0, b = u1;
        if (rem > 2) {
            int s = __ldg(&csr[e + 2]);
            u0 = *reinterpret_cast<const uint2*>(xl + (size_t)s * HCC + chan);
        }
        if (rem > 3) {
            int s = __ldg(&csr[e + 3]);
            u1 = *reinterpret_cast<const uint2*>(xl + (size_t)s * HCC + chan);
        }
        __half2 a0 = *reinterpret_cast<__half2*>(&a.x);
        __half2 a1 = *reinterpret_cast<__half2*>(&a.y);
        __half2 b0 = *reinterpret_cast<__half2*>(&b.x);
        __half2 b1 = *reinterpret_cast<__half2*>(&b.y);
        float xla[4] = {__low2float(a0), __high2float(a0),
                        __low2float(a1), __high2float(a1)};
        float xlb[4] = {__low2float(b0), __high2float(b0),
                        __low2float(b1), __high2float(b1)};
        float sa = 0.f, sb = 0.f;
#pragma unroll
        for (int j = 0; j < 4; ++j) {
            float ta = xla[j] + xrv[j];
            ta = (ta > 0.f) ? ta : NEG_SLOPE * ta;
            sa = fmaf(ta, attv[j], sa);
            float tb = xlb[j] + xrv[j];
            tb = (tb > 0.f) ? tb : NEG_SLOPE * tb;
            sb = fmaf(tb, attv[j], sb);
        }
        sa += __shfl_xor_sync(0xffffffffu, sa, 4);
        sb += __shfl_xor_sync(0xffffffffu, sb, 4);
        sa += __shfl_xor_sync(0xffffffffu, sa, 2);
        sb += __shfl_xor_sync(0xffffffffu, sb, 2);
        sa += __shfl_xor_sync(0xffffffffu, sa, 1);
        sb += __shfl_xor_sync(0xffffffffu, sb, 1);

        // batched online-softmax update (exact)
        float nm = fmaxf(m, fmaxf(sa, sb));
        float scale = __expf(m - nm);
        float pa = __expf(sa - nm);
        float pb = __expf(sb - nm);
        den = den * scale + pa + pb;
#pragma unroll
        for (int j = 0; j < 4; ++j)
            acc[j] = fmaf(acc[j], scale, fmaf(pa, xla[j], pb * xlb[j]));
        m = nm;
        e += 2; rem -= 2;
    }
    if (rem == 1) {
        __half2 a0 = *reinterpret_cast<__half2*>(&u0.x);
        __half2 a1 = *reinterpret_cast<__half2*>(&u0.y);
        float xla[4] = {__low2float(a0), __high2float(a0),
                        __low2float(a1), __high2float(a1)};
        float sa = 0.f;
#pragma unroll
        for (int j = 0; j < 4; ++j) {
            float t = xla[j] + xrv[j];
            t = (t > 0.f) ? t : NEG_SLOPE * t;
            sa = fmaf(t, attv[j], sa);
        }
        sa += __shfl_xor_sync(0xffffffffu, sa, 4);
        sa += __shfl_xor_sync(0xffffffffu, sa, 2);
        sa += __shfl_xor_sync(0xffffffffu, sa, 1);
        float nm = fmaxf(m, sa);
        float scale = __expf(m - nm);
        float p = __expf(sa - nm);
        den = den * scale + p;
#pragma unroll
        for (int j = 0; j < 4; ++j)
            acc[j] = fmaf(acc[j], scale, p * xla[j]);
        m = nm;
    }

    float inv_den = (den > 0.f) ? (1.f / den) : 0.f;
    float o[4];
    {
        uint2 u = *reinterpret_cast<const uint2*>(sk + (size_t)node * HCC + chan);
        __half2 h0 = *reinterpret_cast<__half2*>(&u.x);
        __half2 h1 = *reinterpret_cast<__half2*>(&u.y);
        float skv[4] = {__low2float(h0), __high2float(h0),
                        __low2float(h1), __high2float(h1)};
        float4 c = *reinterpret_cast<const float4*>(cb + chan);
        o[0] = acc[0] * inv_den + c.x + skv[0];
        o[1] = acc[1] * inv_den + c.y + skv[1];
        o[2] = acc[2] * inv_den + c.z + skv[2];
        o[3] = acc[3] * inv_den + c.w + skv[3];
    }

    if (outh) {
        __half2 w0 = __floats2half2_rn(fmaxf(o[0], 0.f), fmaxf(o[1], 0.f));
        __half2 w1 = __floats2half2_rn(fmaxf(o[2], 0.f), fmaxf(o[3], 0.f));
        uint2 u;
        u.x = *reinterpret_cast<uint32_t*>(&w0);
        u.y = *reinterpret_cast<uint32_t*>(&w1);
        *reinterpret_cast<uint2*>(outh + (size_t)node * HCC + chan) = u;
    } else {
        float sq = o[0] * o[0] + o[1] * o[1] + o[2] * o[2] + o[3] * o[3];
#pragma unroll
        for (int off = 16; off > 0; off >>= 1)
            sq += __shfl_xor_sync(0xffffffffu, sq, off);
        float inv = rsqrtf(sq);
        float4 w = make_float4(o[0] * inv, o[1] * inv, o[2] * inv, o[3] * inv);
        *reinterpret_cast<float4*>(outf + (size_t)node * HCC + chan) = w;
    }
}

// ---------------- host ------------------------------------------------------
extern "C" void kernel_launch(void* const* d_in, const int* in_sizes, int n_in,
                              void* d_out, int out_size) {
    const float* x  = (const float*)d_in[0];
    const int*   ei = (const int*)d_in[1];
    const float* W0 = (const float*)d_in[2];

    // f: 3..10, m: 11..18, l: 19..26 (order: Wl, bl, Wr, br, att, cb, Ws, bs)
    const float* P[27];
    for (int i = 3; i < 27; ++i) P[i] = (const float*)d_in[i];

    __half *hh, *xl, *xr, *sk, *Wf, *Wm, *Wl2;
    float *bf, *bm_, *bl2;
    int *deg, *rowptr, *cursor, *csr;
    cudaGetSymbolAddress((void**)&hh,     g_hh);
    cudaGetSymbolAddress((void**)&xl,     g_xl);
    cudaGetSymbolAddress((void**)&xr,     g_xr);
    cudaGetSymbolAddress((void**)&sk,     g_sk);
    cudaGetSymbolAddress((void**)&deg,    g_deg);
    cudaGetSymbolAddress((void**)&rowptr, g_rowptr);
    cudaGetSymbolAddress((void**)&cursor, g_cursor);
    cudaGetSymbolAddress((void**)&csr,    g_csr);
    cudaGetSymbolAddress((void**)&Wf,     g_Wf);
    cudaGetSymbolAddress((void**)&bf,     g_bf);
    cudaGetSymbolAddress((void**)&Wm,     g_Wm);
    cudaGetSymbolAddress((void**)&bm_,    g_bm);
    cudaGetSymbolAddress((void**)&Wl2,    g_Wl2);
    cudaGetSymbolAddress((void**)&bl2,    g_bl2);

    static int smem_set = 0;
    if (!smem_set) {
        cudaFuncSetAttribute(gemm_h16_fused,
                             cudaFuncAttributeMaxDynamicSharedMemorySize, SM_TOTAL);
        smem_set = 1;
    }

    const int* src = ei;
    const int* dst = ei + EE;

    // ---- CSR build (by dst) ----
    zero_int_kernel<<<(NN + 255) / 256, 256>>>(deg, NN);
    hist_kernel<<<(EE + 255) / 256, 256>>>(dst, deg, EE);
    scan_kernel<<<1, 1024>>>(deg, rowptr, cursor, NN);
    scatter_kernel<<<(EE + 255) / 256, 256>>>(src, dst, cursor, csr, EE);

    // ---- pack per-layer weights to fp16 ----
    pack_h_kernel<<<(EMB * 128 + 255) / 256, 256>>>(P[3], P[5], P[9], P[4], P[6], P[10], Wf, bf, EMB);
    pack_h_kernel<<<(HCC * 128 + 255) / 256, 256>>>(P[11], P[13], P[17], P[12], P[14], P[18], Wm, bm_, HCC);
    pack_h_kernel<<<(HCC * 128 + 255) / 256, 256>>>(P[19], P[21], P[25], P[20], P[22], P[26], Wl2, bl2, HCC);

    // h0 = relu(x @ W0)  [N, 32] fp16
    gemm0_kernel<<<(NN + BM - 1) / BM, 256>>>(x, W0, hh, NN, F_IN, EMB);

    int gemm_blocks = (NN + 127) / 128;
    int edge_blocks = (NN * 32 + 255) / 256;

    auto run_layer = [&](const __half* Wp, const float* bp, int K,
                         const float* att, const float* cb,
                         __half* outh, float* outf) {
        gemm_h16_fused<<<gemm_blocks, 256, SM_TOTAL>>>(hh, Wp, bp, xl, xr, sk, NN, K);
        gat_edge_kernel<<<edge_blocks, 256>>>(rowptr, csr, xl, xr, sk, att, cb,
                                              outh, outf, NN);
    };

    run_layer(Wf,  bf,  EMB, P[7],  P[8],  hh, nullptr);   // first GAT layer (K=32)
    run_layer(Wm,  bm_, HCC, P[15], P[16], hh, nullptr);   // mid x3 (shared weights)
    run_layer(Wm,  bm_, HCC, P[15], P[16], hh, nullptr);
    run_layer(Wm,  bm_, HCC, P[15], P[16], hh, nullptr);
    run_layer(Wl2, bl2, HCC, P[23], P[24], nullptr, (float*)d_out);  // last + L2 norm
}